// round 11
// baseline (speedup 1.0000x reference)
#include <cuda_runtime.h>
#include <math.h>

// Problem constants (fixed by the dataset)
#define Bn 2048
#define Dn 1024
#define Hn 2048
#define En 16
#define Wn 4
#define Rn 8
#define MAXK 4
#define CANDMAX 16
#define SCALE_C 1.0f

// ---------------- scratch (device globals; no allocation allowed) -----------
__device__ float g_hpre[Bn * Hn];
__device__ float g_outpre[Bn * Dn];
__device__ float g_cand_val[Bn * CANDMAX];
__device__ unsigned long long g_pack[Bn];
__device__ int   g_assigned_idx[Bn * MAXK];
__device__ float g_assigned_w[Bn * MAXK];
// bf16 (pair-packed) copies
__device__ unsigned g_z_bf[Bn * Dn / 2];
__device__ unsigned g_w1_bf[Hn * Dn / 2];
__device__ unsigned g_w2_bf[Dn * Hn / 2];
__device__ unsigned g_hpre_bf[Bn * Hn / 2];
__device__ unsigned g_a1_bf[En * Wn * Rn * Dn / 2];
__device__ unsigned g_b1_bf[En * Wn * Hn * Rn / 2];
__device__ unsigned g_a2t_bf[En * Wn * (Hn / 2) * Rn];  // [ew][hp][r] transposed
__device__ unsigned g_b2_bf[En * Wn * Dn * Rn / 2];

// ---------------- output layout ----------------
struct Outs {
    float *z, *probs, *mask, *aidx, *aw, *chr, *ev_e, *ev_a;
};
__host__ __device__ __forceinline__ Outs make_outs(float* o, int k) {
    Outs s;
    s.z     = o; o += Bn * Dn;
    s.probs = o; o += Bn * En;
    s.mask  = o; o += Bn * En;
    s.aidx  = o; o += Bn * k;
    s.aw    = o; o += Bn * k;
    s.chr   = o; o += 1;
    s.ev_e  = o; o += (size_t)k * Bn;
    s.ev_a  = o;
    return s;
}

__device__ __forceinline__ float warp_reduce(float v) {
    #pragma unroll
    for (int off = 16; off; off >>= 1) v += __shfl_xor_sync(0xffffffffu, v, off);
    return v;
}
// fast silu (continuous outputs only; softmax keeps exact expf)
__device__ __forceinline__ float silu_f(float x) { return x / (1.0f + __expf(-x)); }

__device__ __forceinline__ unsigned pack_bf16(float lo, float hi) {
    unsigned r;
    asm("cvt.rn.bf16x2.f32 %0, %1, %2;" : "=r"(r) : "f"(hi), "f"(lo));
    return r;
}
__device__ __forceinline__ float bf_lo(unsigned u) { return __uint_as_float(u << 16); }
__device__ __forceinline__ float bf_hi(unsigned u) { return __uint_as_float(u & 0xffff0000u); }

__device__ __forceinline__ void mma_bf16(float* d, const unsigned* a, const unsigned* b) {
    asm volatile(
        "mma.sync.aligned.m16n8k16.row.col.f32.bf16.bf16.f32 "
        "{%0,%1,%2,%3}, {%4,%5,%6,%7}, {%8,%9}, {%0,%1,%2,%3};"
        : "+f"(d[0]), "+f"(d[1]), "+f"(d[2]), "+f"(d[3])
        : "r"(a[0]), "r"(a[1]), "r"(a[2]), "r"(a[3]), "r"(b[0]), "r"(b[1]));
}

__device__ __forceinline__ void cp_async16(unsigned* smem_dst, const void* gmem_src) {
    unsigned saddr = (unsigned)__cvta_generic_to_shared(smem_dst);
    asm volatile("cp.async.cg.shared.global [%0], [%1], 16;" :: "r"(saddr), "l"(gmem_src));
}
#define CP_COMMIT() asm volatile("cp.async.commit_group;")
#define CP_WAIT2()  asm volatile("cp.async.wait_group 2;")

// =====================================================================
// Convert kernel (serial, gates GEMM1): z + fc1_w only (16 MB).
// =====================================================================
#define CVZ (Bn * Dn / 2)
#define CVZW (CVZ + Hn * Dn / 2)

__global__ void __launch_bounds__(256)
convert_zw1_kernel(const float* __restrict__ z, const float* __restrict__ w1) {
    for (int idx = blockIdx.x * 256 + threadIdx.x; idx < CVZW; idx += gridDim.x * 256) {
        if (idx < CVZ) {
            float2 v = ((const float2*)z)[idx];
            g_z_bf[idx] = pack_bf16(v.x, v.y);
        } else {
            float2 v = ((const float2*)w1)[idx - CVZ];
            g_w1_bf[idx - CVZ] = pack_bf16(v.x, v.y);
        }
    }
}

// =====================================================================
// Side convert (runs inside GEMM1's grid): w2, a1, b1, b2 elementwise;
// a2 transposed-packed into [ew][hp][r]:
//   u = pack(a2[ew,r,2hp], a2[ew,r,2hp+1]); dst[ew*8192 + hp*8 + r] = u
// (reads = contiguous float2 at linear index; writes 4B-strided).
// =====================================================================
#define NC0 (Dn * Hn / 2)                       // w2
#define NC1 (NC0 + En * Wn * Rn * Dn / 2)       // a1
#define NC2 (NC1 + En * Wn * Hn * Rn / 2)       // b1
#define NC3 (NC2 + En * Wn * Dn * Rn / 2)       // b2
#define NC4 (NC3 + En * Wn * Rn * Hn / 2)       // a2 (transposed dest)

__device__ void convert_rest_body(int cblk, int tid, int nthreads,
                                  const float* __restrict__ w2,
                                  const float* __restrict__ a1,
                                  const float* __restrict__ b1,
                                  const float* __restrict__ a2,
                                  const float* __restrict__ b2) {
    for (int idx = cblk * 256 + tid; idx < NC4; idx += nthreads) {
        if (idx < NC3) {
            const float2* s; unsigned* d; int off;
            if      (idx < NC0) { s = (const float2*)w2; d = g_w2_bf; off = idx; }
            else if (idx < NC1) { s = (const float2*)a1; d = g_a1_bf; off = idx - NC0; }
            else if (idx < NC2) { s = (const float2*)b1; d = g_b1_bf; off = idx - NC1; }
            else                { s = (const float2*)b2; d = g_b2_bf; off = idx - NC2; }
            float2 v = s[off];
            d[off] = pack_bf16(v.x, v.y);
        } else {
            int local = idx - NC3;               // linear float2 index into a2
            float2 v = ((const float2*)a2)[local];
            int ew = local >> 13;                // 8192 pairs per (e,w)
            int r  = (local >> 10) & 7;
            int hp = local & 1023;
            g_a2t_bf[ew * 8192 + hp * 8 + r] = pack_bf16(v.x, v.y);
        }
    }
}

// =====================================================================
// Side work A: logits/softmax/top-cand (fp32), one warp per token.
// =====================================================================
__device__ void logits_body(int b, int lane,
                            const float* __restrict__ z,
                            const float* __restrict__ proto,
                            const float* __restrict__ ebias,
                            const int* __restrict__ topk_p,
                            const int* __restrict__ ban_p,
                            const float* __restrict__ tau_p,
                            const float* __restrict__ eps_p,
                            float* __restrict__ d_out) {
    const float* zr = z + (size_t)b * Dn;

    float acc[En];
    #pragma unroll
    for (int e = 0; e < En; e++) acc[e] = 0.0f;
    for (int d = lane; d < Dn; d += 32) {
        float zv = zr[d];
        #pragma unroll
        for (int e = 0; e < En; e++) acc[e] += zv * proto[e * Dn + d];
    }
    #pragma unroll
    for (int e = 0; e < En; e++) acc[e] = warp_reduce(acc[e]);

    if (lane != 0) return;

    int k = *topk_p; if (k > En) k = En; if (k > MAXK) k = MAXK; if (k < 1) k = 1;
    int cand_k = 4 * k; if (cand_k < k) cand_k = k; if (cand_k > En) cand_k = En;
    int ban = *ban_p;
    float inv_tau = 1.0f / fmaxf(*tau_p, 1e-6f);
    float eps = *eps_p;

    float lg[En];
    float mx = -1e30f;
    #pragma unroll
    for (int e = 0; e < En; e++) {
        float v = acc[e] * inv_tau + ebias[e];
        if (e == ban) v = -1e9f;
        lg[e] = v;
        mx = fmaxf(mx, v);
    }
    float sum = 0.0f;
    #pragma unroll
    for (int e = 0; e < En; e++) { lg[e] = expf(lg[e] - mx); sum += lg[e]; }
    float inv = 1.0f / sum;

    Outs O = make_outs(d_out, k);
    float pr[En];
    #pragma unroll
    for (int e = 0; e < En; e++) {
        pr[e] = (1.0f - eps) * (lg[e] * inv) + eps / (float)En;
        O.probs[b * En + e] = pr[e];
        O.mask[b * En + e]  = 0.0f;
    }

    bool used[En];
    #pragma unroll
    for (int e = 0; e < En; e++) used[e] = false;
    unsigned long long pk = 0ull;
    for (int j = 0; j < cand_k; j++) {
        float bv = -1e30f; int bi = 0;
        for (int e = 0; e < En; e++)
            if (!used[e] && pr[e] > bv) { bv = pr[e]; bi = e; }
        used[bi] = true;
        g_cand_val[b * CANDMAX + j] = bv;
        pk |= ((unsigned long long)bi) << (4 * j);
    }
    g_pack[b] = pk;

    for (int s = 0; s < k; s++) {
        g_assigned_idx[b * MAXK + s] = -1;
        g_assigned_w[b * MAXK + s]   = 0.0f;
        O.aidx[b * k + s] = -1.0f;
        O.aw[b * k + s]   = 0.0f;
        O.ev_e[s * Bn + b] = -1.0f;
        O.ev_a[s * Bn + b] = -1.0f;
    }
}

// =====================================================================
// Side work B: batched greedy capacity router (single warp).
// =====================================================================
__device__ void route_body(int lane,
                           const int* __restrict__ topk_p,
                           const int* __restrict__ cap_p,
                           float* __restrict__ d_out) {
    int k = *topk_p; if (k > En) k = En; if (k > MAXK) k = MAXK; if (k < 1) k = 1;
    int cand_k = 4 * k; if (cand_k < k) cand_k = k; if (cand_k > En) cand_k = En;
    int cap_lim = *cap_p; if (cap_lim < 1) cap_lim = 1;

    Outs O = make_outs(d_out, k);

    int cap = 0;
    unsigned closed = 0;
    int hits = 0;

    int t0 = 0;
    while (t0 < Bn) {
        const int t = t0 + lane;
        const bool has = (t < Bn);
        unsigned long long pk = has ? g_pack[t] : 0ull;

        unsigned take = 0, slotcand = 0;
        int nslots = 0, myhits = 0;
        if (has) {
            for (int j = 0; j < cand_k; j++) {
                int e = (int)((pk >> (4 * j)) & 15ull);
                if (!((closed >> e) & 1u) && nslots < k) {
                    take |= (1u << e);
                    slotcand |= ((unsigned)j) << (4 * nslots);
                    if (j > 0) myhits++;
                    nslots++;
                }
            }
        }

        unsigned mybits = 0;
        #pragma unroll
        for (int e = 0; e < En; e++) {
            unsigned bb = __ballot_sync(0xffffffffu, (take >> e) & 1u);
            if (lane == e) mybits = bb;
        }
        int cnt = __popc(mybits);

        bool viol = (lane < En) && !((closed >> lane) & 1u) && (cap + cnt > cap_lim);
        unsigned vm = __ballot_sync(0xffffffffu, viol);
        int pstar = 32;
        if (vm) {
            int myp = 32;
            if (viol) {
                int rem = cap_lim - cap;
                unsigned m = mybits;
                for (int i = 0; i < rem; i++) m &= m - 1;
                myp = __ffs(m) - 1;
            }
            #pragma unroll
            for (int off = 16; off; off >>= 1) {
                int o = __shfl_xor_sync(0xffffffffu, myp, off);
                myp = min(myp, o);
            }
            pstar = myp;
        }

        unsigned commit_prefix = (pstar >= 32) ? 0xffffffffu : ((1u << pstar) - 1u);
        if (lane < En) cap += __popc(mybits & commit_prefix);

        if (has && lane < pstar) {
            for (int s = 0; s < nslots; s++) {
                int j = (int)((slotcand >> (4 * s)) & 15u);
                int e = (int)((pk >> (4 * j)) & 15ull);
                float v = g_cand_val[t * CANDMAX + j];
                g_assigned_idx[t * MAXK + s] = e;
                g_assigned_w[t * MAXK + s]   = v;
                O.aidx[t * k + s] = (float)e;
                O.aw[t * k + s]   = v;
                O.ev_e[s * Bn + t] = (float)e;
                O.mask[t * En + e] = 1.0f;
            }
            hits += myhits;
        }

        closed = __ballot_sync(0xffffffffu, (lane < En) && (cap >= cap_lim)) & 0xffffu;
        t0 += pstar;
    }

    #pragma unroll
    for (int off = 16; off; off >>= 1) hits += __shfl_xor_sync(0xffffffffu, hits, off);
    if (lane == 0) O.chr[0] = (float)hits / (float)(Bn * k);
}

// =====================================================================
// Fused BF16 GEMM (cp.async 4-stage pipeline) + side work.
// Block tile 128x64x32, 8 warps, warp tile 32x32, m16n8k16.
// SMEM pitch 20 uints/row (conflict-free). 4 stages = 61,440 B.
// SIDE==1: bx in [NX,NX+16) logits; bx in [NX+16,NX+24) convert-rest.
// SIDE==2: bx==NX router block.
// =====================================================================
#define TBM 128
#define TBN 64
#define TBK 32
#define PITCH 20
#define STG ((TBM + TBN) * PITCH)
#define NSTAGE 4

template <int ACT, int SIDE, int NX>
__global__ void __launch_bounds__(256, 2)
gemm_fused_kernel(const unsigned short* __restrict__ Abf,
                  const unsigned short* __restrict__ Wbf,
                  const float* __restrict__ bias, float* __restrict__ C,
                  unsigned* __restrict__ Cbf,
                  int M, int N, int K,
                  const float* __restrict__ z, const float* __restrict__ proto,
                  const float* __restrict__ ebias,
                  const int* __restrict__ topk_p, const int* __restrict__ ban_p,
                  const float* __restrict__ tau_p, const float* __restrict__ eps_p,
                  const int* __restrict__ cap_p,
                  const float* __restrict__ cw2, const float* __restrict__ ca1,
                  const float* __restrict__ cb1, const float* __restrict__ ca2,
                  const float* __restrict__ cb2,
                  float* __restrict__ d_out) {
    const int bx = blockIdx.x;
    const int by = blockIdx.y;
    const int tid = threadIdx.x;
    const int warp = tid >> 5;
    const int lane = tid & 31;

    if (bx >= NX) {
        if (SIDE == 1) {
            if (bx < NX + 16) {
                int blk = (bx - NX) * gridDim.y + by;
                int b = blk * 8 + warp;
                if (b < Bn)
                    logits_body(b, lane, z, proto, ebias, topk_p, ban_p, tau_p, eps_p, d_out);
            } else {
                int cblk = (bx - NX - 16) * gridDim.y + by;   // 0..127
                convert_rest_body(cblk, tid, 128 * 256, cw2, ca1, cb1, ca2, cb2);
            }
        } else if (SIDE == 2) {
            if (by == 0 && warp == 0)
                route_body(lane, topk_p, cap_p, d_out);
        }
        return;
    }

    extern __shared__ unsigned smem_u[];

    const int g  = lane >> 2;
    const int tg = lane & 3;
    const int wq  = warp & 3;
    const int wn2 = warp >> 2;

    float acc[2][4][4];
    #pragma unroll
    for (int i = 0; i < 2; i++)
        #pragma unroll
        for (int j = 0; j < 4; j++)
            #pragma unroll
            for (int c = 0; c < 4; c++) acc[i][j][c] = 0.0f;

    auto issue = [&](int buf, int kt) {
        unsigned* base = smem_u + buf * STG;
        const int k0 = kt * TBK;
        #pragma unroll
        for (int i = 0; i < 3; i++) {
            int c = tid + i * 256;
            int row = c >> 2, ch = c & 3;
            const unsigned short* src;
            if (row < TBM) src = Abf + (size_t)(by * TBM + row) * K + k0 + ch * 8;
            else           src = Wbf + (size_t)(bx * TBN + row - TBM) * K + k0 + ch * 8;
            cp_async16(base + row * PITCH + ch * 4, (const void*)src);
        }
    };

    const int KIT = K / TBK;
    #pragma unroll
    for (int s = 0; s < NSTAGE - 1; s++) {
        if (s < KIT) issue(s, s);
        CP_COMMIT();
    }

    for (int kt = 0; kt < KIT; kt++) {
        CP_WAIT2();
        __syncthreads();
        if (kt + NSTAGE - 1 < KIT) issue((kt + NSTAGE - 1) & 3, kt + NSTAGE - 1);
        CP_COMMIT();

        const unsigned* AsC = smem_u + (kt & 3) * STG;
        const unsigned* BsC = AsC + TBM * PITCH;

        #pragma unroll
        for (int kk = 0; kk < 2; kk++) {
            unsigned afr[2][4];
            #pragma unroll
            for (int mi = 0; mi < 2; mi++) {
                int row = wq * 32 + mi * 16 + g;
                afr[mi][0] = AsC[row * PITCH + kk * 8 + tg];
                afr[mi][1] = AsC[(row + 8) * PITCH + kk * 8 + tg];
                afr[mi][2] = AsC[row * PITCH + kk * 8 + tg + 4];
                afr[mi][3] = AsC[(row + 8) * PITCH + kk * 8 + tg + 4];
            }
            unsigned bfr[4][2];
            #pragma unroll
            for (int ni = 0; ni < 4; ni++) {
                int col = wn2 * 32 + ni * 8 + g;
                bfr[ni][0] = BsC[col * PITCH + kk * 8 + tg];
                bfr[ni][1] = BsC[col * PITCH + kk * 8 + tg + 4];
            }
            #pragma unroll
            for (int mi = 0; mi < 2; mi++)
                #pragma unroll
                for (int ni = 0; ni < 4; ni++)
                    mma_bf16(acc[mi][ni], afr[mi], bfr[ni]);
        }
    }

    #pragma unroll
    for (int mi = 0; mi < 2; mi++) {
        int row0 = by * TBM + wq * 32 + mi * 16 + g;
        #pragma unroll
        for (int ni = 0; ni < 4; ni++) {
            int col = bx * TBN + wn2 * 32 + ni * 8 + 2 * tg;
            float b0 = bias[col], b1 = bias[col + 1];
            float v0 = acc[mi][ni][0] + b0;
            float v1 = acc[mi][ni][1] + b1;
            float v2 = acc[mi][ni][2] + b0;
            float v3 = acc[mi][ni][3] + b1;
            if (ACT) { v0 = silu_f(v0); v1 = silu_f(v1); v2 = silu_f(v2); v3 = silu_f(v3); }
            *(float2*)(&C[(size_t)row0 * N + col])       = make_float2(v0, v1);
            *(float2*)(&C[(size_t)(row0 + 8) * N + col]) = make_float2(v2, v3);
            if (ACT) {
                Cbf[((size_t)row0 * N + col) >> 1]       = pack_bf16(v0, v1);
                Cbf[((size_t)(row0 + 8) * N + col) >> 1] = pack_bf16(v2, v3);
            }
        }
    }
}

// =====================================================================
// Adapter kernel (R10 structure; A2 loads via transposed [hp][r] layout:
// 8 scalar LDG.32 -> 2 LDG.128 per h-pair iteration).
// =====================================================================
__global__ void __launch_bounds__(256)
adapter_kernel(const float* __restrict__ z,
               const float* __restrict__ ak,
               const unsigned* __restrict__ a1b, const unsigned* __restrict__ b1b,
               const unsigned* __restrict__ a2tb, const unsigned* __restrict__ b2b,
               const int* __restrict__ topk_p,
               float* __restrict__ d_out) {
    __shared__ float s_z[Dn];
    __shared__ float s_hp[Hn];
    __shared__ float s_t1[2][Rn];
    __shared__ float s_t2p[2][4][Rn];
    __shared__ float s_sc[2][Wn];
    __shared__ int   s_base[2];
    __shared__ float s_wgt[2];
    __shared__ int   s_valid[2];

    const int b = blockIdx.x;
    const int tid = threadIdx.x;
    const int lane = tid & 31;
    const int warp = tid >> 5;
    const int group = warp >> 2;
    const int wig = warp & 3;
    const int gt = tid & 127;

    int k = *topk_p; if (k > En) k = En; if (k > MAXK) k = MAXK; if (k < 1) k = 1;
    Outs O = make_outs(d_out, k);

    for (int i = tid; i < Dn; i += 256) s_z[i] = z[(size_t)b * Dn + i];
    for (int i = tid; i < Hn; i += 256) s_hp[i] = g_hpre[(size_t)b * Hn + i];

    float opre[Dn / 256];
    float accd[Dn / 256];
    #pragma unroll
    for (int i = 0; i < Dn / 256; i++) {
        opre[i] = g_outpre[(size_t)b * Dn + tid + i * 256];
        accd[i] = 0.0f;
    }
    __syncthreads();

    for (int s0 = 0; s0 < k; s0 += 2) {
        const int sA = s0 + group;
        const bool act = (sA < k);
        int e = -1;
        float wgt = 0.0f;
        if (act) {
            e   = g_assigned_idx[b * MAXK + sA];
            wgt = g_assigned_w[b * MAXK + sA];
        }
        const bool valid = act && (e >= 0);

        // phase 1: adapter-key dots (fp32)
        if (valid) {
            const float* akr = ak + (size_t)(e * Wn + wig) * Dn;
            float p0 = 0.0f, p1 = 0.0f;
            for (int d = lane; d < Dn; d += 64) {
                p0 += s_z[d] * akr[d];
                p1 += s_z[d + 32] * akr[d + 32];
            }
            float p = warp_reduce(p0 + p1);
            if (lane == 0) s_sc[group][wig] = p;
        }
        __syncthreads();

        // phase 2: argmax + publish
        if (gt == 0) {
            if (valid) {
                float bv = s_sc[group][0]; int bi = 0;
                #pragma unroll
                for (int w2 = 1; w2 < Wn; w2++)
                    if (s_sc[group][w2] > bv) { bv = s_sc[group][w2]; bi = w2; }
                s_base[group] = e * Wn + bi;
                s_wgt[group] = wgt;
                s_valid[group] = 1;
                O.ev_a[sA * Bn + b] = (float)bi;
            } else {
                s_valid[group] = 0;
            }
        }
        __syncthreads();

        const int base = s_base[group];

        // phase 3: t1[r] = z . A1[base, r, :]  (bf16 weights, warp = 2 r's)
        if (valid) {
            const uint2* A1r0 = (const uint2*)a1b + ((size_t)base * Rn + 2 * wig) * (Dn / 4);
            const uint2* A1r1 = A1r0 + (Dn / 4);
            float q0 = 0.0f, q1 = 0.0f;
            #pragma unroll
            for (int i = 0; i < Dn / 128; i++) {
                int idx = lane + i * 32;
                float4 zz = *(const float4*)&s_z[idx * 4];
                uint2 u0 = A1r0[idx], u1 = A1r1[idx];
                q0 += zz.x * bf_lo(u0.x) + zz.y * bf_hi(u0.x)
                    + zz.z * bf_lo(u0.y) + zz.w * bf_hi(u0.y);
                q1 += zz.x * bf_lo(u1.x) + zz.y * bf_hi(u1.x)
                    + zz.z * bf_lo(u1.y) + zz.w * bf_hi(u1.y);
            }
            q0 = warp_reduce(q0);
            q1 = warp_reduce(q1);
            if (lane == 0) { s_t1[group][2 * wig] = q0; s_t1[group][2 * wig + 1] = q1; }
        }
        __syncthreads();

        // phase 4' (merged): warp owns h pairs [wig*256, wig*256+256).
        if (valid) {
            float t1r[Rn];
            #pragma unroll
            for (int r = 0; r < Rn; r++) t1r[r] = s_t1[group][r];
            float t2p[Rn];
            #pragma unroll
            for (int r = 0; r < Rn; r++) t2p[r] = 0.0f;
            const uint4* B1 = (const uint4*)b1b + (size_t)base * Hn;
            const uint4* A2t = (const uint4*)a2tb + (size_t)base * 2048;  // 2 uint4 per hp
            #pragma unroll
            for (int i = 0; i < 8; i++) {
                int hp = wig * 256 + lane + i * 32;    // pair index
                float2 h2 = *(const float2*)&s_hp[2 * hp];
                uint4 q0 = B1[2 * hp];
                uint4 q1 = B1[2 * hp + 1];
                float d10 = t1r[0] * bf_lo(q0.x) + t1r[1] * bf_hi(q0.x)
                          + t1r[2] * bf_lo(q0.y) + t1r[3] * bf_hi(q0.y)
                          + t1r[4] * bf_lo(q0.z) + t1r[5] * bf_hi(q0.z)
                          + t1r[6] * bf_lo(q0.w) + t1r[7] * bf_hi(q0.w);
                float d11 = t1r[0] * bf_lo(q1.x) + t1r[1] * bf_hi(q1.x)
                          + t1r[2] * bf_lo(q1.y) + t1r[3] * bf_hi(q1.y)
                          + t1r[4] * bf_lo(q1.z) + t1r[5] * bf_hi(q1.z)
                          + t1r[6] * bf_lo(q1.w) + t1r[7] * bf_hi(q1.w);
                float hv0 = silu_f(h2.x + d10 * SCALE_C);
                float hv1 = silu_f(h2.y + d11 * SCALE_C);
                uint4 a20 = A2t[2 * hp];
                uint4 a21 = A2t[2 * hp + 1];
                t2p[0] += hv0 * bf_lo(a20.x) + hv1 * bf_hi(a20.x);
                t2p[1] += hv0 * bf_lo(a20.y) + hv1 * bf_hi(a20.y);
                t2p[2] += hv0 * bf_lo(a20.z) + hv1 * bf_hi(a20.z);
                t2p[3] += hv0 * bf_lo(a20.w) + hv1 * bf_hi(a20.w);
                t2p[4] += hv0 * bf_lo(a21.x) + hv1 * bf_hi(a21.x);
                t2p[5] += hv0 * bf_lo(a21.y) + hv1 * bf_hi(a21.y);
                t2p[6] += hv0 * bf_lo(a21.z) + hv1 * bf_hi(a21.z);
                t2p[7] += hv0 * bf_lo(a21.w) + hv1 * bf_hi(a21.w);
            }
            #pragma unroll
            for (int r = 0; r < Rn; r++) t2p[r] = warp_reduce(t2p[r]);
            if (lane < Rn) s_t2p[group][wig][lane] = t2p[lane];
        }
        __syncthreads();

        // phase 6: accumulate both groups' deltas into per-thread acc
        #pragma unroll
        for (int gg = 0; gg < 2; gg++) {
            if (s_valid[gg]) {
                const int bs = s_base[gg];
                const float wg = s_wgt[gg];
                float t2r[Rn];
                #pragma unroll
                for (int r = 0; r < Rn; r++)
                    t2r[r] = s_t2p[gg][0][r] + s_t2p[gg][1][r]
                           + s_t2p[gg][2][r] + s_t2p[gg][3][r];
                const uint4* B2q = (const uint4*)b2b + (size_t)bs * Dn;
                #pragma unroll
                for (int i = 0; i < Dn / 256; i++) {
                    int d = tid + i * 256;
                    uint4 q = B2q[d];
                    float d2 = t2r[0] * bf_lo(q.x) + t2r[1] * bf_hi(q.x)
                             + t2r[2] * bf_lo(q.y) + t2r[3] * bf_hi(q.y)
                             + t2r[4] * bf_lo(q.z) + t2r[5] * bf_hi(q.z)
                             + t2r[6] * bf_lo(q.w) + t2r[7] * bf_hi(q.w);
                    accd[i] += wg * (opre[i] + d2 * SCALE_C);
                }
            }
        }
        __syncthreads();
    }

    #pragma unroll
    for (int i = 0; i < Dn / 256; i++) {
        int d = tid + i * 256;
        O.z[(size_t)b * Dn + d] = s_z[d] + accd[i];
    }
}

// =====================================================================
// launch
// =====================================================================
extern "C" void kernel_launch(void* const* d_in, const int* in_sizes, int n_in,
                              void* d_out, int out_size) {
    const float* z     = (const float*)d_in[0];
    const int*   topk  = (const int*)  d_in[1];
    const int*   cap   = (const int*)  d_in[2];
    const int*   ban   = (const int*)  d_in[3];
    const float* tau   = (const float*)d_in[4];
    const float* eps   = (const float*)d_in[5];
    const float* fc1w  = (const float*)d_in[6];
    const float* fc1b  = (const float*)d_in[7];
    const float* fc2w  = (const float*)d_in[8];
    const float* fc2b  = (const float*)d_in[9];
    const float* proto = (const float*)d_in[10];
    const float* ak    = (const float*)d_in[11];
    const float* ebias = (const float*)d_in[12];
    const float* a1    = (const float*)d_in[13];
    const float* b1    = (const float*)d_in[14];
    const float* a2    = (const float*)d_in[15];
    const float* b2    = (const float*)d_in[16];
    float* out = (float*)d_out;

    float *hpre_ptr, *outpre_ptr;
    unsigned *zb, *w1b, *w2b, *hpb, *a1b, *b1b, *a2tb, *b2b;
    cudaGetSymbolAddress((void**)&hpre_ptr, g_hpre);
    cudaGetSymbolAddress((void**)&outpre_ptr, g_outpre);
    cudaGetSymbolAddress((void**)&zb,   g_z_bf);
    cudaGetSymbolAddress((void**)&w1b,  g_w1_bf);
    cudaGetSymbolAddress((void**)&w2b,  g_w2_bf);
    cudaGetSymbolAddress((void**)&hpb,  g_hpre_bf);
    cudaGetSymbolAddress((void**)&a1b,  g_a1_bf);
    cudaGetSymbolAddress((void**)&b1b,  g_b1_bf);
    cudaGetSymbolAddress((void**)&a2tb, g_a2t_bf);
    cudaGetSymbolAddress((void**)&b2b,  g_b2_bf);

    const int gemm_smem = NSTAGE * STG * sizeof(unsigned);  // 61440
    cudaFuncSetAttribute((const void*)gemm_fused_kernel<1, 1, 32>,
                         cudaFuncAttributeMaxDynamicSharedMemorySize, gemm_smem);
    cudaFuncSetAttribute((const void*)gemm_fused_kernel<0, 2, 16>,
                         cudaFuncAttributeMaxDynamicSharedMemorySize, gemm_smem);

    // 0) serial convert: z + fc1_w only (gates GEMM1)
    convert_zw1_kernel<<<1024, 256>>>(z, fc1w);

    // 1) GEMM1 (h_pre) + logits side blocks + convert-rest side blocks
    //    grid: 32 gemm cols + 16 logits cols + 8 convert cols
    gemm_fused_kernel<1, 1, 32><<<dim3(56, 16), 256, gemm_smem>>>(
        (const unsigned short*)zb, (const unsigned short*)w1b, fc1b,
        hpre_ptr, hpb, Bn, Hn, Dn,
        z, proto, ebias, topk, ban, tau, eps, cap,
        fc2w, a1, b1, a2, b2, out);

    // 2) GEMM2 (out_pre) + router side block
    gemm_fused_kernel<0, 2, 16><<<dim3(17, 16), 256, gemm_smem>>>(
        (const unsigned short*)hpb, (const unsigned short*)w2b, fc2b,
        outpre_ptr, nullptr, Bn, Dn, Hn,
        z, proto, ebias, topk, ban, tau, eps, cap,
        nullptr, nullptr, nullptr, nullptr, nullptr, out);

    // 3) adapter select + LoRA deltas + final combine
    adapter_kernel<<<Bn, 256>>>(z, ak, a1b, b1b, a2tb, b2b, topk, out);
}

// round 12
// speedup vs baseline: 1.0937x; 1.0937x over previous
#include <cuda_runtime.h>
#include <math.h>

// Problem constants (fixed by the dataset)
#define Bn 2048
#define Dn 1024
#define Hn 2048
#define En 16
#define Wn 4
#define Rn 8
#define MAXK 4
#define CANDMAX 16
#define SCALE_C 1.0f

// ---------------- scratch (device globals; no allocation allowed) -----------
__device__ float g_hpre[Bn * Hn];
__device__ float g_outpre[Bn * Dn];
__device__ float g_cand_val[Bn * CANDMAX];
__device__ unsigned long long g_pack[Bn];
__device__ int   g_assigned_idx[Bn * MAXK];
__device__ float g_assigned_w[Bn * MAXK];
// bf16 (pair-packed) copies
__device__ unsigned g_z_bf[Bn * Dn / 2];
__device__ unsigned g_w1_bf[Hn * Dn / 2];
__device__ unsigned g_w2_bf[Dn * Hn / 2];
__device__ unsigned g_hpre_bf[Bn * Hn / 2];
__device__ unsigned g_a1_bf[En * Wn * Rn * Dn / 2];
__device__ unsigned g_b1_bf[En * Wn * Hn * Rn / 2];
__device__ unsigned g_a2_bf[En * Wn * Rn * Hn / 2];
__device__ unsigned g_b2_bf[En * Wn * Dn * Rn / 2];

// ---------------- output layout ----------------
struct Outs {
    float *z, *probs, *mask, *aidx, *aw, *chr, *ev_e, *ev_a;
};
__host__ __device__ __forceinline__ Outs make_outs(float* o, int k) {
    Outs s;
    s.z     = o; o += Bn * Dn;
    s.probs = o; o += Bn * En;
    s.mask  = o; o += Bn * En;
    s.aidx  = o; o += Bn * k;
    s.aw    = o; o += Bn * k;
    s.chr   = o; o += 1;
    s.ev_e  = o; o += (size_t)k * Bn;
    s.ev_a  = o;
    return s;
}

__device__ __forceinline__ float warp_reduce(float v) {
    #pragma unroll
    for (int off = 16; off; off >>= 1) v += __shfl_xor_sync(0xffffffffu, v, off);
    return v;
}
// fast silu (continuous outputs only; softmax keeps exact expf)
__device__ __forceinline__ float silu_f(float x) { return x / (1.0f + __expf(-x)); }

__device__ __forceinline__ unsigned pack_bf16(float lo, float hi) {
    unsigned r;
    asm("cvt.rn.bf16x2.f32 %0, %1, %2;" : "=r"(r) : "f"(hi), "f"(lo));
    return r;
}
__device__ __forceinline__ float bf_lo(unsigned u) { return __uint_as_float(u << 16); }
__device__ __forceinline__ float bf_hi(unsigned u) { return __uint_as_float(u & 0xffff0000u); }

__device__ __forceinline__ void mma_bf16(float* d, const unsigned* a, const unsigned* b) {
    asm volatile(
        "mma.sync.aligned.m16n8k16.row.col.f32.bf16.bf16.f32 "
        "{%0,%1,%2,%3}, {%4,%5,%6,%7}, {%8,%9}, {%0,%1,%2,%3};"
        : "+f"(d[0]), "+f"(d[1]), "+f"(d[2]), "+f"(d[3])
        : "r"(a[0]), "r"(a[1]), "r"(a[2]), "r"(a[3]), "r"(b[0]), "r"(b[1]));
}

__device__ __forceinline__ void cp_async16(unsigned* smem_dst, const void* gmem_src) {
    unsigned saddr = (unsigned)__cvta_generic_to_shared(smem_dst);
    asm volatile("cp.async.cg.shared.global [%0], [%1], 16;" :: "r"(saddr), "l"(gmem_src));
}
#define CP_COMMIT() asm volatile("cp.async.commit_group;")
#define CP_WAIT2()  asm volatile("cp.async.wait_group 2;")

// =====================================================================
// Serial convert (gates GEMM1): z + fc1_w only (16 MB).
// =====================================================================
#define CVZ (Bn * Dn / 2)
#define CVZW (CVZ + Hn * Dn / 2)

__global__ void __launch_bounds__(256)
convert_zw1_kernel(const float* __restrict__ z, const float* __restrict__ w1) {
    for (int idx = blockIdx.x * 256 + threadIdx.x; idx < CVZW; idx += gridDim.x * 256) {
        if (idx < CVZ) {
            float2 v = ((const float2*)z)[idx];
            g_z_bf[idx] = pack_bf16(v.x, v.y);
        } else {
            float2 v = ((const float2*)w1)[idx - CVZ];
            g_w1_bf[idx - CVZ] = pack_bf16(v.x, v.y);
        }
    }
}

// =====================================================================
// Side convert (inside GEMM1's grid): w2, a1, b1, a2, b2 — ELEMENTWISE
// only (coalesced reads AND writes; no transpose).
// =====================================================================
#define NC0 (Dn * Hn / 2)                       // w2
#define NC1 (NC0 + En * Wn * Rn * Dn / 2)       // a1
#define NC2 (NC1 + En * Wn * Hn * Rn / 2)       // b1
#define NC3 (NC2 + En * Wn * Rn * Hn / 2)       // a2
#define NC4 (NC3 + En * Wn * Dn * Rn / 2)       // b2

__device__ void convert_rest_body(int cblk, int tid, int nthreads,
                                  const float* __restrict__ w2,
                                  const float* __restrict__ a1,
                                  const float* __restrict__ b1,
                                  const float* __restrict__ a2,
                                  const float* __restrict__ b2) {
    for (int idx = cblk * 256 + tid; idx < NC4; idx += nthreads) {
        const float2* s; unsigned* d; int off;
        if      (idx < NC0) { s = (const float2*)w2; d = g_w2_bf; off = idx; }
        else if (idx < NC1) { s = (const float2*)a1; d = g_a1_bf; off = idx - NC0; }
        else if (idx < NC2) { s = (const float2*)b1; d = g_b1_bf; off = idx - NC1; }
        else if (idx < NC3) { s = (const float2*)a2; d = g_a2_bf; off = idx - NC2; }
        else                { s = (const float2*)b2; d = g_b2_bf; off = idx - NC3; }
        float2 v = s[off];
        d[off] = pack_bf16(v.x, v.y);
    }
}

// =====================================================================
// Side work A: logits/softmax/top-cand (fp32), one warp per token.
// =====================================================================
__device__ void logits_body(int b, int lane,
                            const float* __restrict__ z,
                            const float* __restrict__ proto,
                            const float* __restrict__ ebias,
                            const int* __restrict__ topk_p,
                            const int* __restrict__ ban_p,
                            const float* __restrict__ tau_p,
                            const float* __restrict__ eps_p,
                            float* __restrict__ d_out) {
    const float* zr = z + (size_t)b * Dn;

    float acc[En];
    #pragma unroll
    for (int e = 0; e < En; e++) acc[e] = 0.0f;
    for (int d = lane; d < Dn; d += 32) {
        float zv = zr[d];
        #pragma unroll
        for (int e = 0; e < En; e++) acc[e] += zv * proto[e * Dn + d];
    }
    #pragma unroll
    for (int e = 0; e < En; e++) acc[e] = warp_reduce(acc[e]);

    if (lane != 0) return;

    int k = *topk_p; if (k > En) k = En; if (k > MAXK) k = MAXK; if (k < 1) k = 1;
    int cand_k = 4 * k; if (cand_k < k) cand_k = k; if (cand_k > En) cand_k = En;
    int ban = *ban_p;
    float inv_tau = 1.0f / fmaxf(*tau_p, 1e-6f);
    float eps = *eps_p;

    float lg[En];
    float mx = -1e30f;
    #pragma unroll
    for (int e = 0; e < En; e++) {
        float v = acc[e] * inv_tau + ebias[e];
        if (e == ban) v = -1e9f;
        lg[e] = v;
        mx = fmaxf(mx, v);
    }
    float sum = 0.0f;
    #pragma unroll
    for (int e = 0; e < En; e++) { lg[e] = expf(lg[e] - mx); sum += lg[e]; }
    float inv = 1.0f / sum;

    Outs O = make_outs(d_out, k);
    float pr[En];
    #pragma unroll
    for (int e = 0; e < En; e++) {
        pr[e] = (1.0f - eps) * (lg[e] * inv) + eps / (float)En;
        O.probs[b * En + e] = pr[e];
        O.mask[b * En + e]  = 0.0f;
    }

    bool used[En];
    #pragma unroll
    for (int e = 0; e < En; e++) used[e] = false;
    unsigned long long pk = 0ull;
    for (int j = 0; j < cand_k; j++) {
        float bv = -1e30f; int bi = 0;
        for (int e = 0; e < En; e++)
            if (!used[e] && pr[e] > bv) { bv = pr[e]; bi = e; }
        used[bi] = true;
        g_cand_val[b * CANDMAX + j] = bv;
        pk |= ((unsigned long long)bi) << (4 * j);
    }
    g_pack[b] = pk;

    for (int s = 0; s < k; s++) {
        g_assigned_idx[b * MAXK + s] = -1;
        g_assigned_w[b * MAXK + s]   = 0.0f;
        O.aidx[b * k + s] = -1.0f;
        O.aw[b * k + s]   = 0.0f;
        O.ev_e[s * Bn + b] = -1.0f;
        O.ev_a[s * Bn + b] = -1.0f;
    }
}

// =====================================================================
// Side work B: batched greedy capacity router (single warp).
// =====================================================================
__device__ void route_body(int lane,
                           const int* __restrict__ topk_p,
                           const int* __restrict__ cap_p,
                           float* __restrict__ d_out) {
    int k = *topk_p; if (k > En) k = En; if (k > MAXK) k = MAXK; if (k < 1) k = 1;
    int cand_k = 4 * k; if (cand_k < k) cand_k = k; if (cand_k > En) cand_k = En;
    int cap_lim = *cap_p; if (cap_lim < 1) cap_lim = 1;

    Outs O = make_outs(d_out, k);

    int cap = 0;
    unsigned closed = 0;
    int hits = 0;

    int t0 = 0;
    while (t0 < Bn) {
        const int t = t0 + lane;
        const bool has = (t < Bn);
        unsigned long long pk = has ? g_pack[t] : 0ull;

        unsigned take = 0, slotcand = 0;
        int nslots = 0, myhits = 0;
        if (has) {
            for (int j = 0; j < cand_k; j++) {
                int e = (int)((pk >> (4 * j)) & 15ull);
                if (!((closed >> e) & 1u) && nslots < k) {
                    take |= (1u << e);
                    slotcand |= ((unsigned)j) << (4 * nslots);
                    if (j > 0) myhits++;
                    nslots++;
                }
            }
        }

        unsigned mybits = 0;
        #pragma unroll
        for (int e = 0; e < En; e++) {
            unsigned bb = __ballot_sync(0xffffffffu, (take >> e) & 1u);
            if (lane == e) mybits = bb;
        }
        int cnt = __popc(mybits);

        bool viol = (lane < En) && !((closed >> lane) & 1u) && (cap + cnt > cap_lim);
        unsigned vm = __ballot_sync(0xffffffffu, viol);
        int pstar = 32;
        if (vm) {
            int myp = 32;
            if (viol) {
                int rem = cap_lim - cap;
                unsigned m = mybits;
                for (int i = 0; i < rem; i++) m &= m - 1;
                myp = __ffs(m) - 1;
            }
            #pragma unroll
            for (int off = 16; off; off >>= 1) {
                int o = __shfl_xor_sync(0xffffffffu, myp, off);
                myp = min(myp, o);
            }
            pstar = myp;
        }

        unsigned commit_prefix = (pstar >= 32) ? 0xffffffffu : ((1u << pstar) - 1u);
        if (lane < En) cap += __popc(mybits & commit_prefix);

        if (has && lane < pstar) {
            for (int s = 0; s < nslots; s++) {
                int j = (int)((slotcand >> (4 * s)) & 15u);
                int e = (int)((pk >> (4 * j)) & 15ull);
                float v = g_cand_val[t * CANDMAX + j];
                g_assigned_idx[t * MAXK + s] = e;
                g_assigned_w[t * MAXK + s]   = v;
                O.aidx[t * k + s] = (float)e;
                O.aw[t * k + s]   = v;
                O.ev_e[s * Bn + t] = (float)e;
                O.mask[t * En + e] = 1.0f;
            }
            hits += myhits;
        }

        closed = __ballot_sync(0xffffffffu, (lane < En) && (cap >= cap_lim)) & 0xffffu;
        t0 += pstar;
    }

    #pragma unroll
    for (int off = 16; off; off >>= 1) hits += __shfl_xor_sync(0xffffffffu, hits, off);
    if (lane == 0) O.chr[0] = (float)hits / (float)(Bn * k);
}

// =====================================================================
// Fused BF16 GEMM (cp.async 4-stage pipeline) + side work.
// Block tile 128x64x32, 8 warps, warp tile 32x32, m16n8k16.
// SMEM pitch 20 uints/row (conflict-free). 4 stages = 61,440 B.
// SIDE==1: bx in [NX,NX+16) logits; bx in [NX+16,NX+32) convert-rest.
// SIDE==2: bx==NX router block.
// =====================================================================
#define TBM 128
#define TBN 64
#define TBK 32
#define PITCH 20
#define STG ((TBM + TBN) * PITCH)
#define NSTAGE 4

template <int ACT, int SIDE, int NX>
__global__ void __launch_bounds__(256, 2)
gemm_fused_kernel(const unsigned short* __restrict__ Abf,
                  const unsigned short* __restrict__ Wbf,
                  const float* __restrict__ bias, float* __restrict__ C,
                  unsigned* __restrict__ Cbf,
                  int M, int N, int K,
                  const float* __restrict__ z, const float* __restrict__ proto,
                  const float* __restrict__ ebias,
                  const int* __restrict__ topk_p, const int* __restrict__ ban_p,
                  const float* __restrict__ tau_p, const float* __restrict__ eps_p,
                  const int* __restrict__ cap_p,
                  const float* __restrict__ cw2, const float* __restrict__ ca1,
                  const float* __restrict__ cb1, const float* __restrict__ ca2,
                  const float* __restrict__ cb2,
                  float* __restrict__ d_out) {
    const int bx = blockIdx.x;
    const int by = blockIdx.y;
    const int tid = threadIdx.x;
    const int warp = tid >> 5;
    const int lane = tid & 31;

    if (bx >= NX) {
        if (SIDE == 1) {
            if (bx < NX + 16) {
                int blk = (bx - NX) * gridDim.y + by;
                int b = blk * 8 + warp;
                if (b < Bn)
                    logits_body(b, lane, z, proto, ebias, topk_p, ban_p, tau_p, eps_p, d_out);
            } else {
                int cblk = (bx - NX - 16) * gridDim.y + by;   // 0..255
                convert_rest_body(cblk, tid, 256 * 256, cw2, ca1, cb1, ca2, cb2);
            }
        } else if (SIDE == 2) {
            if (by == 0 && warp == 0)
                route_body(lane, topk_p, cap_p, d_out);
        }
        return;
    }

    extern __shared__ unsigned smem_u[];

    const int g  = lane >> 2;
    const int tg = lane & 3;
    const int wq  = warp & 3;
    const int wn2 = warp >> 2;

    float acc[2][4][4];
    #pragma unroll
    for (int i = 0; i < 2; i++)
        #pragma unroll
        for (int j = 0; j < 4; j++)
            #pragma unroll
            for (int c = 0; c < 4; c++) acc[i][j][c] = 0.0f;

    auto issue = [&](int buf, int kt) {
        unsigned* base = smem_u + buf * STG;
        const int k0 = kt * TBK;
        #pragma unroll
        for (int i = 0; i < 3; i++) {
            int c = tid + i * 256;
            int row = c >> 2, ch = c & 3;
            const unsigned short* src;
            if (row < TBM) src = Abf + (size_t)(by * TBM + row) * K + k0 + ch * 8;
            else           src = Wbf + (size_t)(bx * TBN + row - TBM) * K + k0 + ch * 8;
            cp_async16(base + row * PITCH + ch * 4, (const void*)src);
        }
    };

    const int KIT = K / TBK;
    #pragma unroll
    for (int s = 0; s < NSTAGE - 1; s++) {
        if (s < KIT) issue(s, s);
        CP_COMMIT();
    }

    for (int kt = 0; kt < KIT; kt++) {
        CP_WAIT2();
        __syncthreads();
        if (kt + NSTAGE - 1 < KIT) issue((kt + NSTAGE - 1) & 3, kt + NSTAGE - 1);
        CP_COMMIT();

        const unsigned* AsC = smem_u + (kt & 3) * STG;
        const unsigned* BsC = AsC + TBM * PITCH;

        #pragma unroll
        for (int kk = 0; kk < 2; kk++) {
            unsigned afr[2][4];
            #pragma unroll
            for (int mi = 0; mi < 2; mi++) {
                int row = wq * 32 + mi * 16 + g;
                afr[mi][0] = AsC[row * PITCH + kk * 8 + tg];
                afr[mi][1] = AsC[(row + 8) * PITCH + kk * 8 + tg];
                afr[mi][2] = AsC[row * PITCH + kk * 8 + tg + 4];
                afr[mi][3] = AsC[(row + 8) * PITCH + kk * 8 + tg + 4];
            }
            unsigned bfr[4][2];
            #pragma unroll
            for (int ni = 0; ni < 4; ni++) {
                int col = wn2 * 32 + ni * 8 + g;
                bfr[ni][0] = BsC[col * PITCH + kk * 8 + tg];
                bfr[ni][1] = BsC[col * PITCH + kk * 8 + tg + 4];
            }
            #pragma unroll
            for (int mi = 0; mi < 2; mi++)
                #pragma unroll
                for (int ni = 0; ni < 4; ni++)
                    mma_bf16(acc[mi][ni], afr[mi], bfr[ni]);
        }
    }

    #pragma unroll
    for (int mi = 0; mi < 2; mi++) {
        int row0 = by * TBM + wq * 32 + mi * 16 + g;
        #pragma unroll
        for (int ni = 0; ni < 4; ni++) {
            int col = bx * TBN + wn2 * 32 + ni * 8 + 2 * tg;
            float b0 = bias[col], b1 = bias[col + 1];
            float v0 = acc[mi][ni][0] + b0;
            float v1 = acc[mi][ni][1] + b1;
            float v2 = acc[mi][ni][2] + b0;
            float v3 = acc[mi][ni][3] + b1;
            if (ACT) { v0 = silu_f(v0); v1 = silu_f(v1); v2 = silu_f(v2); v3 = silu_f(v3); }
            *(float2*)(&C[(size_t)row0 * N + col])       = make_float2(v0, v1);
            *(float2*)(&C[(size_t)(row0 + 8) * N + col]) = make_float2(v2, v3);
            if (ACT) {
                Cbf[((size_t)row0 * N + col) >> 1]       = pack_bf16(v0, v1);
                Cbf[((size_t)(row0 + 8) * N + col) >> 1] = pack_bf16(v2, v3);
            }
        }
    }
}

// =====================================================================
// Adapter kernel (exact round-10 version: best measured, 65 us).
// =====================================================================
__global__ void __launch_bounds__(256)
adapter_kernel(const float* __restrict__ z,
               const float* __restrict__ ak,
               const unsigned* __restrict__ a1b, const unsigned* __restrict__ b1b,
               const unsigned* __restrict__ a2b, const unsigned* __restrict__ b2b,
               const int* __restrict__ topk_p,
               float* __restrict__ d_out) {
    __shared__ float s_z[Dn];
    __shared__ float s_hp[Hn];
    __shared__ float s_t1[2][Rn];
    __shared__ float s_t2p[2][4][Rn];
    __shared__ float s_sc[2][Wn];
    __shared__ int   s_base[2];
    __shared__ float s_wgt[2];
    __shared__ int   s_valid[2];

    const int b = blockIdx.x;
    const int tid = threadIdx.x;
    const int lane = tid & 31;
    const int warp = tid >> 5;
    const int group = warp >> 2;
    const int wig = warp & 3;
    const int gt = tid & 127;

    int k = *topk_p; if (k > En) k = En; if (k > MAXK) k = MAXK; if (k < 1) k = 1;
    Outs O = make_outs(d_out, k);

    for (int i = tid; i < Dn; i += 256) s_z[i] = z[(size_t)b * Dn + i];
    for (int i = tid; i < Hn; i += 256) s_hp[i] = g_hpre[(size_t)b * Hn + i];

    float opre[Dn / 256];
    float accd[Dn / 256];
    #pragma unroll
    for (int i = 0; i < Dn / 256; i++) {
        opre[i] = g_outpre[(size_t)b * Dn + tid + i * 256];
        accd[i] = 0.0f;
    }
    __syncthreads();

    for (int s0 = 0; s0 < k; s0 += 2) {
        const int sA = s0 + group;
        const bool act = (sA < k);
        int e = -1;
        float wgt = 0.0f;
        if (act) {
            e   = g_assigned_idx[b * MAXK + sA];
            wgt = g_assigned_w[b * MAXK + sA];
        }
        const bool valid = act && (e >= 0);

        // phase 1: adapter-key dots (fp32)
        if (valid) {
            const float* akr = ak + (size_t)(e * Wn + wig) * Dn;
            float p0 = 0.0f, p1 = 0.0f;
            for (int d = lane; d < Dn; d += 64) {
                p0 += s_z[d] * akr[d];
                p1 += s_z[d + 32] * akr[d + 32];
            }
            float p = warp_reduce(p0 + p1);
            if (lane == 0) s_sc[group][wig] = p;
        }
        __syncthreads();

        // phase 2: argmax + publish
        if (gt == 0) {
            if (valid) {
                float bv = s_sc[group][0]; int bi = 0;
                #pragma unroll
                for (int w2 = 1; w2 < Wn; w2++)
                    if (s_sc[group][w2] > bv) { bv = s_sc[group][w2]; bi = w2; }
                s_base[group] = e * Wn + bi;
                s_wgt[group] = wgt;
                s_valid[group] = 1;
                O.ev_a[sA * Bn + b] = (float)bi;
            } else {
                s_valid[group] = 0;
            }
        }
        __syncthreads();

        const int base = s_base[group];

        // phase 3: t1[r] = z . A1[base, r, :]  (bf16 weights, warp = 2 r's)
        if (valid) {
            const uint2* A1r0 = (const uint2*)a1b + ((size_t)base * Rn + 2 * wig) * (Dn / 4);
            const uint2* A1r1 = A1r0 + (Dn / 4);
            float q0 = 0.0f, q1 = 0.0f;
            #pragma unroll
            for (int i = 0; i < Dn / 128; i++) {
                int idx = lane + i * 32;
                float4 zz = *(const float4*)&s_z[idx * 4];
                uint2 u0 = A1r0[idx], u1 = A1r1[idx];
                q0 += zz.x * bf_lo(u0.x) + zz.y * bf_hi(u0.x)
                    + zz.z * bf_lo(u0.y) + zz.w * bf_hi(u0.y);
                q1 += zz.x * bf_lo(u1.x) + zz.y * bf_hi(u1.x)
                    + zz.z * bf_lo(u1.y) + zz.w * bf_hi(u1.y);
            }
            q0 = warp_reduce(q0);
            q1 = warp_reduce(q1);
            if (lane == 0) { s_t1[group][2 * wig] = q0; s_t1[group][2 * wig + 1] = q1; }
        }
        __syncthreads();

        // phase 4' (merged): warp owns h pairs [wig*256, wig*256+256).
        if (valid) {
            float t1r[Rn];
            #pragma unroll
            for (int r = 0; r < Rn; r++) t1r[r] = s_t1[group][r];
            float t2p[Rn];
            #pragma unroll
            for (int r = 0; r < Rn; r++) t2p[r] = 0.0f;
            const uint4* B1 = (const uint4*)b1b + (size_t)base * Hn;
            const unsigned* A2 = a2b + (size_t)base * Rn * (Hn / 2);
            #pragma unroll
            for (int i = 0; i < 8; i++) {
                int hp = wig * 256 + lane + i * 32;    // pair index
                float2 h2 = *(const float2*)&s_hp[2 * hp];
                uint4 q0 = B1[2 * hp];
                uint4 q1 = B1[2 * hp + 1];
                float d10 = t1r[0] * bf_lo(q0.x) + t1r[1] * bf_hi(q0.x)
                          + t1r[2] * bf_lo(q0.y) + t1r[3] * bf_hi(q0.y)
                          + t1r[4] * bf_lo(q0.z) + t1r[5] * bf_hi(q0.z)
                          + t1r[6] * bf_lo(q0.w) + t1r[7] * bf_hi(q0.w);
                float d11 = t1r[0] * bf_lo(q1.x) + t1r[1] * bf_hi(q1.x)
                          + t1r[2] * bf_lo(q1.y) + t1r[3] * bf_hi(q1.y)
                          + t1r[4] * bf_lo(q1.z) + t1r[5] * bf_hi(q1.z)
                          + t1r[6] * bf_lo(q1.w) + t1r[7] * bf_hi(q1.w);
                float hv0 = silu_f(h2.x + d10 * SCALE_C);
                float hv1 = silu_f(h2.y + d11 * SCALE_C);
                #pragma unroll
                for (int r = 0; r < Rn; r++) {
                    unsigned u = A2[r * (Hn / 2) + hp];
                    t2p[r] += hv0 * bf_lo(u) + hv1 * bf_hi(u);
                }
            }
            #pragma unroll
            for (int r = 0; r < Rn; r++) t2p[r] = warp_reduce(t2p[r]);
            if (lane < Rn) s_t2p[group][wig][lane] = t2p[lane];
        }
        __syncthreads();

        // phase 6: accumulate both groups' deltas into per-thread acc
        #pragma unroll
        for (int gg = 0; gg < 2; gg++) {
            if (s_valid[gg]) {
                const int bs = s_base[gg];
                const float wg = s_wgt[gg];
                float t2r[Rn];
                #pragma unroll
                for (int r = 0; r < Rn; r++)
                    t2r[r] = s_t2p[gg][0][r] + s_t2p[gg][1][r]
                           + s_t2p[gg][2][r] + s_t2p[gg][3][r];
                const uint4* B2q = (const uint4*)b2b + (size_t)bs * Dn;
                #pragma unroll
                for (int i = 0; i < Dn / 256; i++) {
                    int d = tid + i * 256;
                    uint4 q = B2q[d];
                    float d2 = t2r[0] * bf_lo(q.x) + t2r[1] * bf_hi(q.x)
                             + t2r[2] * bf_lo(q.y) + t2r[3] * bf_hi(q.y)
                             + t2r[4] * bf_lo(q.z) + t2r[5] * bf_hi(q.z)
                             + t2r[6] * bf_lo(q.w) + t2r[7] * bf_hi(q.w);
                    accd[i] += wg * (opre[i] + d2 * SCALE_C);
                }
            }
        }
        __syncthreads();
    }

    #pragma unroll
    for (int i = 0; i < Dn / 256; i++) {
        int d = tid + i * 256;
        O.z[(size_t)b * Dn + d] = s_z[d] + accd[i];
    }
}

// =====================================================================
// launch
// =====================================================================
extern "C" void kernel_launch(void* const* d_in, const int* in_sizes, int n_in,
                              void* d_out, int out_size) {
    const float* z     = (const float*)d_in[0];
    const int*   topk  = (const int*)  d_in[1];
    const int*   cap   = (const int*)  d_in[2];
    const int*   ban   = (const int*)  d_in[3];
    const float* tau   = (const float*)d_in[4];
    const float* eps   = (const float*)d_in[5];
    const float* fc1w  = (const float*)d_in[6];
    const float* fc1b  = (const float*)d_in[7];
    const float* fc2w  = (const float*)d_in[8];
    const float* fc2b  = (const float*)d_in[9];
    const float* proto = (const float*)d_in[10];
    const float* ak    = (const float*)d_in[11];
    const float* ebias = (const float*)d_in[12];
    const float* a1    = (const float*)d_in[13];
    const float* b1    = (const float*)d_in[14];
    const float* a2    = (const float*)d_in[15];
    const float* b2    = (const float*)d_in[16];
    float* out = (float*)d_out;

    float *hpre_ptr, *outpre_ptr;
    unsigned *zb, *w1b, *w2b, *hpb, *a1b, *b1b, *a2b, *b2b;
    cudaGetSymbolAddress((void**)&hpre_ptr, g_hpre);
    cudaGetSymbolAddress((void**)&outpre_ptr, g_outpre);
    cudaGetSymbolAddress((void**)&zb,  g_z_bf);
    cudaGetSymbolAddress((void**)&w1b, g_w1_bf);
    cudaGetSymbolAddress((void**)&w2b, g_w2_bf);
    cudaGetSymbolAddress((void**)&hpb, g_hpre_bf);
    cudaGetSymbolAddress((void**)&a1b, g_a1_bf);
    cudaGetSymbolAddress((void**)&b1b, g_b1_bf);
    cudaGetSymbolAddress((void**)&a2b, g_a2_bf);
    cudaGetSymbolAddress((void**)&b2b, g_b2_bf);

    const int gemm_smem = NSTAGE * STG * sizeof(unsigned);  // 61440
    cudaFuncSetAttribute((const void*)gemm_fused_kernel<1, 1, 32>,
                         cudaFuncAttributeMaxDynamicSharedMemorySize, gemm_smem);
    cudaFuncSetAttribute((const void*)gemm_fused_kernel<0, 2, 16>,
                         cudaFuncAttributeMaxDynamicSharedMemorySize, gemm_smem);

    // 0) serial convert: z + fc1_w only (gates GEMM1)
    convert_zw1_kernel<<<1024, 256>>>(z, fc1w);

    // 1) GEMM1 (h_pre) + logits side blocks + convert-rest side blocks
    //    grid: 32 gemm cols + 16 logits cols + 16 convert cols
    gemm_fused_kernel<1, 1, 32><<<dim3(64, 16), 256, gemm_smem>>>(
        (const unsigned short*)zb, (const unsigned short*)w1b, fc1b,
        hpre_ptr, hpb, Bn, Hn, Dn,
        z, proto, ebias, topk, ban, tau, eps, cap,
        fc2w, a1, b1, a2, b2, out);

    // 2) GEMM2 (out_pre) + router side block
    gemm_fused_kernel<0, 2, 16><<<dim3(17, 16), 256, gemm_smem>>>(
        (const unsigned short*)hpb, (const unsigned short*)w2b, fc2b,
        outpre_ptr, nullptr, Bn, Dn, Hn,
        z, proto, ebias, topk, ban, tau, eps, cap,
        nullptr, nullptr, nullptr, nullptr, nullptr, out);

    // 3) adapter select + LoRA deltas + final combine (round-10 exact)
    adapter_kernel<<<Bn, 256>>>(z, ak, a1b, b1b, a2b, b2b, topk, out);
}

// round 13
// speedup vs baseline: 1.1486x; 1.0502x over previous
#include <cuda_runtime.h>
#include <math.h>

// Problem constants (fixed by the dataset)
#define Bn 2048
#define Dn 1024
#define Hn 2048
#define En 16
#define Wn 4
#define Rn 8
#define MAXK 4
#define CANDMAX 16
#define SCALE_C 1.0f

// ---------------- scratch (device globals; no allocation allowed) -----------
__device__ float g_hpre[Bn * Hn];
__device__ float g_outpre[Bn * Dn];
__device__ float g_cand_val[Bn * CANDMAX];
__device__ unsigned long long g_pack[Bn];
__device__ int   g_assigned_idx[Bn * MAXK];
__device__ float g_assigned_w[Bn * MAXK];
// bf16 (pair-packed) copies
__device__ unsigned g_z_bf[Bn * Dn / 2];
__device__ unsigned g_w1_bf[Hn * Dn / 2];
__device__ unsigned g_w2_bf[Dn * Hn / 2];
__device__ unsigned g_hpre_bf[Bn * Hn / 2];
__device__ unsigned g_a1_bf[En * Wn * Rn * Dn / 2];
__device__ unsigned g_b1_bf[En * Wn * Hn * Rn / 2];
__device__ unsigned g_a2_bf[En * Wn * Rn * Hn / 2];
__device__ unsigned g_b2_bf[En * Wn * Dn * Rn / 2];

// ---------------- output layout ----------------
struct Outs {
    float *z, *probs, *mask, *aidx, *aw, *chr, *ev_e, *ev_a;
};
__host__ __device__ __forceinline__ Outs make_outs(float* o, int k) {
    Outs s;
    s.z     = o; o += Bn * Dn;
    s.probs = o; o += Bn * En;
    s.mask  = o; o += Bn * En;
    s.aidx  = o; o += Bn * k;
    s.aw    = o; o += Bn * k;
    s.chr   = o; o += 1;
    s.ev_e  = o; o += (size_t)k * Bn;
    s.ev_a  = o;
    return s;
}

__device__ __forceinline__ float warp_reduce(float v) {
    #pragma unroll
    for (int off = 16; off; off >>= 1) v += __shfl_xor_sync(0xffffffffu, v, off);
    return v;
}
// fast silu (continuous outputs only; softmax keeps exact expf)
__device__ __forceinline__ float silu_f(float x) { return x / (1.0f + __expf(-x)); }

__device__ __forceinline__ unsigned pack_bf16(float lo, float hi) {
    unsigned r;
    asm("cvt.rn.bf16x2.f32 %0, %1, %2;" : "=r"(r) : "f"(hi), "f"(lo));
    return r;
}
__device__ __forceinline__ float bf_lo(unsigned u) { return __uint_as_float(u << 16); }
__device__ __forceinline__ float bf_hi(unsigned u) { return __uint_as_float(u & 0xffff0000u); }

__device__ __forceinline__ void mma_bf16(float* d, const unsigned* a, const unsigned* b) {
    asm volatile(
        "mma.sync.aligned.m16n8k16.row.col.f32.bf16.bf16.f32 "
        "{%0,%1,%2,%3}, {%4,%5,%6,%7}, {%8,%9}, {%0,%1,%2,%3};"
        : "+f"(d[0]), "+f"(d[1]), "+f"(d[2]), "+f"(d[3])
        : "r"(a[0]), "r"(a[1]), "r"(a[2]), "r"(a[3]), "r"(b[0]), "r"(b[1]));
}

__device__ __forceinline__ void cp_async16(unsigned* smem_dst, const void* gmem_src) {
    unsigned saddr = (unsigned)__cvta_generic_to_shared(smem_dst);
    asm volatile("cp.async.cg.shared.global [%0], [%1], 16;" :: "r"(saddr), "l"(gmem_src));
}
#define CP_COMMIT() asm volatile("cp.async.commit_group;")
#define CP_WAIT2()  asm volatile("cp.async.wait_group 2;")
#define GROUP_BAR(id) asm volatile("bar.sync %0, 128;" :: "r"(id) : "memory")

// =====================================================================
// Convert kernel: fp32 -> bf16x2-packed copies (one-time, elementwise).
// =====================================================================
#define CV0 (Bn * Dn / 2)
#define CV1 (CV0 + Hn * Dn / 2)
#define CV2 (CV1 + Dn * Hn / 2)
#define CV3 (CV2 + En * Wn * Rn * Dn / 2)
#define CV4 (CV3 + En * Wn * Hn * Rn / 2)
#define CV5 (CV4 + En * Wn * Rn * Hn / 2)
#define CV6 (CV5 + En * Wn * Dn * Rn / 2)

__global__ void __launch_bounds__(256)
convert_kernel(const float* __restrict__ z,  const float* __restrict__ w1,
               const float* __restrict__ w2, const float* __restrict__ a1,
               const float* __restrict__ b1, const float* __restrict__ a2,
               const float* __restrict__ b2) {
    for (int idx = blockIdx.x * 256 + threadIdx.x; idx < CV6; idx += gridDim.x * 256) {
        const float2* s; unsigned* d; int off;
        if      (idx < CV0) { s = (const float2*)z;  d = g_z_bf;  off = idx; }
        else if (idx < CV1) { s = (const float2*)w1; d = g_w1_bf; off = idx - CV0; }
        else if (idx < CV2) { s = (const float2*)w2; d = g_w2_bf; off = idx - CV1; }
        else if (idx < CV3) { s = (const float2*)a1; d = g_a1_bf; off = idx - CV2; }
        else if (idx < CV4) { s = (const float2*)b1; d = g_b1_bf; off = idx - CV3; }
        else if (idx < CV5) { s = (const float2*)a2; d = g_a2_bf; off = idx - CV4; }
        else                { s = (const float2*)b2; d = g_b2_bf; off = idx - CV5; }
        float2 v = s[off];
        d[off] = pack_bf16(v.x, v.y);
    }
}

// =====================================================================
// Side work A: logits/softmax/top-cand (fp32), one warp per token.
// =====================================================================
__device__ void logits_body(int b, int lane,
                            const float* __restrict__ z,
                            const float* __restrict__ proto,
                            const float* __restrict__ ebias,
                            const int* __restrict__ topk_p,
                            const int* __restrict__ ban_p,
                            const float* __restrict__ tau_p,
                            const float* __restrict__ eps_p,
                            float* __restrict__ d_out) {
    const float* zr = z + (size_t)b * Dn;

    float acc[En];
    #pragma unroll
    for (int e = 0; e < En; e++) acc[e] = 0.0f;
    for (int d = lane; d < Dn; d += 32) {
        float zv = zr[d];
        #pragma unroll
        for (int e = 0; e < En; e++) acc[e] += zv * proto[e * Dn + d];
    }
    #pragma unroll
    for (int e = 0; e < En; e++) acc[e] = warp_reduce(acc[e]);

    if (lane != 0) return;

    int k = *topk_p; if (k > En) k = En; if (k > MAXK) k = MAXK; if (k < 1) k = 1;
    int cand_k = 4 * k; if (cand_k < k) cand_k = k; if (cand_k > En) cand_k = En;
    int ban = *ban_p;
    float inv_tau = 1.0f / fmaxf(*tau_p, 1e-6f);
    float eps = *eps_p;

    float lg[En];
    float mx = -1e30f;
    #pragma unroll
    for (int e = 0; e < En; e++) {
        float v = acc[e] * inv_tau + ebias[e];
        if (e == ban) v = -1e9f;
        lg[e] = v;
        mx = fmaxf(mx, v);
    }
    float sum = 0.0f;
    #pragma unroll
    for (int e = 0; e < En; e++) { lg[e] = expf(lg[e] - mx); sum += lg[e]; }
    float inv = 1.0f / sum;

    Outs O = make_outs(d_out, k);
    float pr[En];
    #pragma unroll
    for (int e = 0; e < En; e++) {
        pr[e] = (1.0f - eps) * (lg[e] * inv) + eps / (float)En;
        O.probs[b * En + e] = pr[e];
        O.mask[b * En + e]  = 0.0f;
    }

    bool used[En];
    #pragma unroll
    for (int e = 0; e < En; e++) used[e] = false;
    unsigned long long pk = 0ull;
    for (int j = 0; j < cand_k; j++) {
        float bv = -1e30f; int bi = 0;
        for (int e = 0; e < En; e++)
            if (!used[e] && pr[e] > bv) { bv = pr[e]; bi = e; }
        used[bi] = true;
        g_cand_val[b * CANDMAX + j] = bv;
        pk |= ((unsigned long long)bi) << (4 * j);
    }
    g_pack[b] = pk;

    for (int s = 0; s < k; s++) {
        g_assigned_idx[b * MAXK + s] = -1;
        g_assigned_w[b * MAXK + s]   = 0.0f;
        O.aidx[b * k + s] = -1.0f;
        O.aw[b * k + s]   = 0.0f;
        O.ev_e[s * Bn + b] = -1.0f;
        O.ev_a[s * Bn + b] = -1.0f;
    }
}

// =====================================================================
// Side work B: batched greedy capacity router (single warp).
// =====================================================================
__device__ void route_body(int lane,
                           const int* __restrict__ topk_p,
                           const int* __restrict__ cap_p,
                           float* __restrict__ d_out) {
    int k = *topk_p; if (k > En) k = En; if (k > MAXK) k = MAXK; if (k < 1) k = 1;
    int cand_k = 4 * k; if (cand_k < k) cand_k = k; if (cand_k > En) cand_k = En;
    int cap_lim = *cap_p; if (cap_lim < 1) cap_lim = 1;

    Outs O = make_outs(d_out, k);

    int cap = 0;
    unsigned closed = 0;
    int hits = 0;

    int t0 = 0;
    while (t0 < Bn) {
        const int t = t0 + lane;
        const bool has = (t < Bn);
        unsigned long long pk = has ? g_pack[t] : 0ull;

        unsigned take = 0, slotcand = 0;
        int nslots = 0, myhits = 0;
        if (has) {
            for (int j = 0; j < cand_k; j++) {
                int e = (int)((pk >> (4 * j)) & 15ull);
                if (!((closed >> e) & 1u) && nslots < k) {
                    take |= (1u << e);
                    slotcand |= ((unsigned)j) << (4 * nslots);
                    if (j > 0) myhits++;
                    nslots++;
                }
            }
        }

        unsigned mybits = 0;
        #pragma unroll
        for (int e = 0; e < En; e++) {
            unsigned bb = __ballot_sync(0xffffffffu, (take >> e) & 1u);
            if (lane == e) mybits = bb;
        }
        int cnt = __popc(mybits);

        bool viol = (lane < En) && !((closed >> lane) & 1u) && (cap + cnt > cap_lim);
        unsigned vm = __ballot_sync(0xffffffffu, viol);
        int pstar = 32;
        if (vm) {
            int myp = 32;
            if (viol) {
                int rem = cap_lim - cap;
                unsigned m = mybits;
                for (int i = 0; i < rem; i++) m &= m - 1;
                myp = __ffs(m) - 1;
            }
            #pragma unroll
            for (int off = 16; off; off >>= 1) {
                int o = __shfl_xor_sync(0xffffffffu, myp, off);
                myp = min(myp, o);
            }
            pstar = myp;
        }

        unsigned commit_prefix = (pstar >= 32) ? 0xffffffffu : ((1u << pstar) - 1u);
        if (lane < En) cap += __popc(mybits & commit_prefix);

        if (has && lane < pstar) {
            for (int s = 0; s < nslots; s++) {
                int j = (int)((slotcand >> (4 * s)) & 15u);
                int e = (int)((pk >> (4 * j)) & 15ull);
                float v = g_cand_val[t * CANDMAX + j];
                g_assigned_idx[t * MAXK + s] = e;
                g_assigned_w[t * MAXK + s]   = v;
                O.aidx[t * k + s] = (float)e;
                O.aw[t * k + s]   = v;
                O.ev_e[s * Bn + t] = (float)e;
                O.mask[t * En + e] = 1.0f;
            }
            hits += myhits;
        }

        closed = __ballot_sync(0xffffffffu, (lane < En) && (cap >= cap_lim)) & 0xffffu;
        t0 += pstar;
    }

    #pragma unroll
    for (int off = 16; off; off >>= 1) hits += __shfl_xor_sync(0xffffffffu, hits, off);
    if (lane == 0) O.chr[0] = (float)hits / (float)(Bn * k);
}

// =====================================================================
// Fused BF16 GEMM (cp.async 4-stage pipeline) + side work (R10 exact).
// SIDE==1: logits side blocks; SIDE==2: router side block.
// =====================================================================
#define TBM 128
#define TBN 64
#define TBK 32
#define PITCH 20
#define STG ((TBM + TBN) * PITCH)
#define NSTAGE 4

template <int ACT, int SIDE, int NX>
__global__ void __launch_bounds__(256, 2)
gemm_fused_kernel(const unsigned short* __restrict__ Abf,
                  const unsigned short* __restrict__ Wbf,
                  const float* __restrict__ bias, float* __restrict__ C,
                  unsigned* __restrict__ Cbf,
                  int M, int N, int K,
                  const float* __restrict__ z, const float* __restrict__ proto,
                  const float* __restrict__ ebias,
                  const int* __restrict__ topk_p, const int* __restrict__ ban_p,
                  const float* __restrict__ tau_p, const float* __restrict__ eps_p,
                  const int* __restrict__ cap_p,
                  float* __restrict__ d_out) {
    const int bx = blockIdx.x;
    const int by = blockIdx.y;
    const int tid = threadIdx.x;
    const int warp = tid >> 5;
    const int lane = tid & 31;

    if (bx >= NX) {
        if (SIDE == 1) {
            int blk = (bx - NX) * gridDim.y + by;
            int b = blk * 8 + warp;
            if (b < Bn)
                logits_body(b, lane, z, proto, ebias, topk_p, ban_p, tau_p, eps_p, d_out);
        } else if (SIDE == 2) {
            if (by == 0 && warp == 0)
                route_body(lane, topk_p, cap_p, d_out);
        }
        return;
    }

    extern __shared__ unsigned smem_u[];

    const int g  = lane >> 2;
    const int tg = lane & 3;
    const int wq  = warp & 3;
    const int wn2 = warp >> 2;

    float acc[2][4][4];
    #pragma unroll
    for (int i = 0; i < 2; i++)
        #pragma unroll
        for (int j = 0; j < 4; j++)
            #pragma unroll
            for (int c = 0; c < 4; c++) acc[i][j][c] = 0.0f;

    auto issue = [&](int buf, int kt) {
        unsigned* base = smem_u + buf * STG;
        const int k0 = kt * TBK;
        #pragma unroll
        for (int i = 0; i < 3; i++) {
            int c = tid + i * 256;
            int row = c >> 2, ch = c & 3;
            const unsigned short* src;
            if (row < TBM) src = Abf + (size_t)(by * TBM + row) * K + k0 + ch * 8;
            else           src = Wbf + (size_t)(bx * TBN + row - TBM) * K + k0 + ch * 8;
            cp_async16(base + row * PITCH + ch * 4, (const void*)src);
        }
    };

    const int KIT = K / TBK;
    #pragma unroll
    for (int s = 0; s < NSTAGE - 1; s++) {
        if (s < KIT) issue(s, s);
        CP_COMMIT();
    }

    for (int kt = 0; kt < KIT; kt++) {
        CP_WAIT2();
        __syncthreads();
        if (kt + NSTAGE - 1 < KIT) issue((kt + NSTAGE - 1) & 3, kt + NSTAGE - 1);
        CP_COMMIT();

        const unsigned* AsC = smem_u + (kt & 3) * STG;
        const unsigned* BsC = AsC + TBM * PITCH;

        #pragma unroll
        for (int kk = 0; kk < 2; kk++) {
            unsigned afr[2][4];
            #pragma unroll
            for (int mi = 0; mi < 2; mi++) {
                int row = wq * 32 + mi * 16 + g;
                afr[mi][0] = AsC[row * PITCH + kk * 8 + tg];
                afr[mi][1] = AsC[(row + 8) * PITCH + kk * 8 + tg];
                afr[mi][2] = AsC[row * PITCH + kk * 8 + tg + 4];
                afr[mi][3] = AsC[(row + 8) * PITCH + kk * 8 + tg + 4];
            }
            unsigned bfr[4][2];
            #pragma unroll
            for (int ni = 0; ni < 4; ni++) {
                int col = wn2 * 32 + ni * 8 + g;
                bfr[ni][0] = BsC[col * PITCH + kk * 8 + tg];
                bfr[ni][1] = BsC[col * PITCH + kk * 8 + tg + 4];
            }
            #pragma unroll
            for (int mi = 0; mi < 2; mi++)
                #pragma unroll
                for (int ni = 0; ni < 4; ni++)
                    mma_bf16(acc[mi][ni], afr[mi], bfr[ni]);
        }
    }

    #pragma unroll
    for (int mi = 0; mi < 2; mi++) {
        int row0 = by * TBM + wq * 32 + mi * 16 + g;
        #pragma unroll
        for (int ni = 0; ni < 4; ni++) {
            int col = bx * TBN + wn2 * 32 + ni * 8 + 2 * tg;
            float b0 = bias[col], b1 = bias[col + 1];
            float v0 = acc[mi][ni][0] + b0;
            float v1 = acc[mi][ni][1] + b1;
            float v2 = acc[mi][ni][2] + b0;
            float v3 = acc[mi][ni][3] + b1;
            if (ACT) { v0 = silu_f(v0); v1 = silu_f(v1); v2 = silu_f(v2); v3 = silu_f(v3); }
            *(float2*)(&C[(size_t)row0 * N + col])       = make_float2(v0, v1);
            *(float2*)(&C[(size_t)(row0 + 8) * N + col]) = make_float2(v2, v3);
            if (ACT) {
                Cbf[((size_t)row0 * N + col) >> 1]       = pack_bf16(v0, v1);
                Cbf[((size_t)(row0 + 8) * N + col) >> 1] = pack_bf16(v2, v3);
            }
        }
    }
}

// =====================================================================
// Adapter kernel (R10 structure + group-local barriers for phases 1-3
// + float4 fp32 loads). One block per token, two slot-groups.
// =====================================================================
__global__ void __launch_bounds__(256)
adapter_kernel(const float* __restrict__ z,
               const float* __restrict__ ak,
               const unsigned* __restrict__ a1b, const unsigned* __restrict__ b1b,
               const unsigned* __restrict__ a2b, const unsigned* __restrict__ b2b,
               const int* __restrict__ topk_p,
               float* __restrict__ d_out) {
    __shared__ float s_z[Dn];
    __shared__ float s_hp[Hn];
    __shared__ float s_t1[2][Rn];
    __shared__ float s_t2p[2][4][Rn];
    __shared__ float s_sc[2][Wn];
    __shared__ int   s_base[2];
    __shared__ float s_wgt[2];
    __shared__ int   s_valid[2];

    const int b = blockIdx.x;
    const int tid = threadIdx.x;
    const int lane = tid & 31;
    const int warp = tid >> 5;
    const int group = warp >> 2;
    const int wig = warp & 3;
    const int gt = tid & 127;
    const int gbar = 1 + group;     // named barrier id for this group

    int k = *topk_p; if (k > En) k = En; if (k > MAXK) k = MAXK; if (k < 1) k = 1;
    Outs O = make_outs(d_out, k);

    // vectorized staging
    for (int i = tid; i < Dn / 4; i += 256)
        ((float4*)s_z)[i] = ((const float4*)(z + (size_t)b * Dn))[i];
    for (int i = tid; i < Hn / 4; i += 256)
        ((float4*)s_hp)[i] = ((const float4*)(g_hpre + (size_t)b * Hn))[i];

    float opre[Dn / 256];
    float accd[Dn / 256];
    #pragma unroll
    for (int i = 0; i < Dn / 256; i++) {
        opre[i] = g_outpre[(size_t)b * Dn + tid + i * 256];
        accd[i] = 0.0f;
    }
    __syncthreads();

    for (int s0 = 0; s0 < k; s0 += 2) {
        const int sA = s0 + group;
        const bool act = (sA < k);
        int e = -1;
        float wgt = 0.0f;
        if (act) {
            e   = g_assigned_idx[b * MAXK + sA];
            wgt = g_assigned_w[b * MAXK + sA];
        }
        const bool valid = act && (e >= 0);

        // phase 1: adapter-key dots (fp32, float4)
        if (valid) {
            const float4* akr = (const float4*)(ak + (size_t)(e * Wn + wig) * Dn);
            float p = 0.0f;
            #pragma unroll
            for (int i = 0; i < Dn / 128; i++) {
                int idx = lane + i * 32;
                float4 a = akr[idx];
                float4 zz = ((const float4*)s_z)[idx];
                p += a.x * zz.x + a.y * zz.y + a.z * zz.z + a.w * zz.w;
            }
            p = warp_reduce(p);
            if (lane == 0) s_sc[group][wig] = p;
        }
        GROUP_BAR(gbar);

        // phase 2: argmax + publish
        if (gt == 0) {
            if (valid) {
                float bv = s_sc[group][0]; int bi = 0;
                #pragma unroll
                for (int w2 = 1; w2 < Wn; w2++)
                    if (s_sc[group][w2] > bv) { bv = s_sc[group][w2]; bi = w2; }
                s_base[group] = e * Wn + bi;
                s_wgt[group] = wgt;
                s_valid[group] = 1;
                O.ev_a[sA * Bn + b] = (float)bi;
            } else {
                s_valid[group] = 0;
            }
        }
        GROUP_BAR(gbar);

        const int base = s_base[group];

        // phase 3: t1[r] = z . A1[base, r, :]  (bf16 weights, warp = 2 r's)
        if (valid) {
            const uint2* A1r0 = (const uint2*)a1b + ((size_t)base * Rn + 2 * wig) * (Dn / 4);
            const uint2* A1r1 = A1r0 + (Dn / 4);
            float q0 = 0.0f, q1 = 0.0f;
            #pragma unroll
            for (int i = 0; i < Dn / 128; i++) {
                int idx = lane + i * 32;
                float4 zz = ((const float4*)s_z)[idx];
                uint2 u0 = A1r0[idx], u1 = A1r1[idx];
                q0 += zz.x * bf_lo(u0.x) + zz.y * bf_hi(u0.x)
                    + zz.z * bf_lo(u0.y) + zz.w * bf_hi(u0.y);
                q1 += zz.x * bf_lo(u1.x) + zz.y * bf_hi(u1.x)
                    + zz.z * bf_lo(u1.y) + zz.w * bf_hi(u1.y);
            }
            q0 = warp_reduce(q0);
            q1 = warp_reduce(q1);
            if (lane == 0) { s_t1[group][2 * wig] = q0; s_t1[group][2 * wig + 1] = q1; }
        }
        GROUP_BAR(gbar);

        // phase 4' (merged): warp owns h pairs [wig*256, wig*256+256).
        if (valid) {
            float t1r[Rn];
            #pragma unroll
            for (int r = 0; r < Rn; r++) t1r[r] = s_t1[group][r];
            float t2p[Rn];
            #pragma unroll
            for (int r = 0; r < Rn; r++) t2p[r] = 0.0f;
            const uint4* B1 = (const uint4*)b1b + (size_t)base * Hn;
            const unsigned* A2 = a2b + (size_t)base * Rn * (Hn / 2);
            #pragma unroll
            for (int i = 0; i < 8; i++) {
                int hp = wig * 256 + lane + i * 32;    // pair index
                float2 h2 = *(const float2*)&s_hp[2 * hp];
                uint4 q0 = B1[2 * hp];
                uint4 q1 = B1[2 * hp + 1];
                float d10 = t1r[0] * bf_lo(q0.x) + t1r[1] * bf_hi(q0.x)
                          + t1r[2] * bf_lo(q0.y) + t1r[3] * bf_hi(q0.y)
                          + t1r[4] * bf_lo(q0.z) + t1r[5] * bf_hi(q0.z)
                          + t1r[6] * bf_lo(q0.w) + t1r[7] * bf_hi(q0.w);
                float d11 = t1r[0] * bf_lo(q1.x) + t1r[1] * bf_hi(q1.x)
                          + t1r[2] * bf_lo(q1.y) + t1r[3] * bf_hi(q1.y)
                          + t1r[4] * bf_lo(q1.z) + t1r[5] * bf_hi(q1.z)
                          + t1r[6] * bf_lo(q1.w) + t1r[7] * bf_hi(q1.w);
                float hv0 = silu_f(h2.x + d10 * SCALE_C);
                float hv1 = silu_f(h2.y + d11 * SCALE_C);
                #pragma unroll
                for (int r = 0; r < Rn; r++) {
                    unsigned u = A2[r * (Hn / 2) + hp];
                    t2p[r] += hv0 * bf_lo(u) + hv1 * bf_hi(u);
                }
            }
            #pragma unroll
            for (int r = 0; r < Rn; r++) t2p[r] = warp_reduce(t2p[r]);
            if (lane < Rn) s_t2p[group][wig][lane] = t2p[lane];
        }
        __syncthreads();   // full barrier: phase 6 reads both groups

        // phase 6: accumulate both groups' deltas into per-thread acc
        #pragma unroll
        for (int gg = 0; gg < 2; gg++) {
            if (s_valid[gg]) {
                const int bs = s_base[gg];
                const float wg = s_wgt[gg];
                float t2r[Rn];
                #pragma unroll
                for (int r = 0; r < Rn; r++)
                    t2r[r] = s_t2p[gg][0][r] + s_t2p[gg][1][r]
                           + s_t2p[gg][2][r] + s_t2p[gg][3][r];
                const uint4* B2q = (const uint4*)b2b + (size_t)bs * Dn;
                #pragma unroll
                for (int i = 0; i < Dn / 256; i++) {
                    int d = tid + i * 256;
                    uint4 q = B2q[d];
                    float d2 = t2r[0] * bf_lo(q.x) + t2r[1] * bf_hi(q.x)
                             + t2r[2] * bf_lo(q.y) + t2r[3] * bf_hi(q.y)
                             + t2r[4] * bf_lo(q.z) + t2r[5] * bf_hi(q.z)
                             + t2r[6] * bf_lo(q.w) + t2r[7] * bf_hi(q.w);
                    accd[i] += wg * (opre[i] + d2 * SCALE_C);
                }
            }
        }
        __syncthreads();
    }

    #pragma unroll
    for (int i = 0; i < Dn / 256; i++) {
        int d = tid + i * 256;
        O.z[(size_t)b * Dn + d] = s_z[d] + accd[i];
    }
}

// =====================================================================
// launch  (exact round-10 structure = best measured config)
// =====================================================================
extern "C" void kernel_launch(void* const* d_in, const int* in_sizes, int n_in,
                              void* d_out, int out_size) {
    const float* z     = (const float*)d_in[0];
    const int*   topk  = (const int*)  d_in[1];
    const int*   cap   = (const int*)  d_in[2];
    const int*   ban   = (const int*)  d_in[3];
    const float* tau   = (const float*)d_in[4];
    const float* eps   = (const float*)d_in[5];
    const float* fc1w  = (const float*)d_in[6];
    const float* fc1b  = (const float*)d_in[7];
    const float* fc2w  = (const float*)d_in[8];
    const float* fc2b  = (const float*)d_in[9];
    const float* proto = (const float*)d_in[10];
    const float* ak    = (const float*)d_in[11];
    const float* ebias = (const float*)d_in[12];
    const float* a1    = (const float*)d_in[13];
    const float* b1    = (const float*)d_in[14];
    const float* a2    = (const float*)d_in[15];
    const float* b2    = (const float*)d_in[16];
    float* out = (float*)d_out;

    float *hpre_ptr, *outpre_ptr;
    unsigned *zb, *w1b, *w2b, *hpb, *a1b, *b1b, *a2b, *b2b;
    cudaGetSymbolAddress((void**)&hpre_ptr, g_hpre);
    cudaGetSymbolAddress((void**)&outpre_ptr, g_outpre);
    cudaGetSymbolAddress((void**)&zb,  g_z_bf);
    cudaGetSymbolAddress((void**)&w1b, g_w1_bf);
    cudaGetSymbolAddress((void**)&w2b, g_w2_bf);
    cudaGetSymbolAddress((void**)&hpb, g_hpre_bf);
    cudaGetSymbolAddress((void**)&a1b, g_a1_bf);
    cudaGetSymbolAddress((void**)&b1b, g_b1_bf);
    cudaGetSymbolAddress((void**)&a2b, g_a2_bf);
    cudaGetSymbolAddress((void**)&b2b, g_b2_bf);

    const int gemm_smem = NSTAGE * STG * sizeof(unsigned);  // 61440
    cudaFuncSetAttribute((const void*)gemm_fused_kernel<1, 1, 32>,
                         cudaFuncAttributeMaxDynamicSharedMemorySize, gemm_smem);
    cudaFuncSetAttribute((const void*)gemm_fused_kernel<0, 2, 16>,
                         cudaFuncAttributeMaxDynamicSharedMemorySize, gemm_smem);

    // 0) one-time fp32 -> bf16 conversion
    convert_kernel<<<2048, 256>>>(z, fc1w, fc2w, a1, b1, a2, b2);

    // 1) h_pre = silu(z @ fc1_w^T + fc1_b) (+ bf16 copy) + logits side work
    gemm_fused_kernel<1, 1, 32><<<dim3(48, 16), 256, gemm_smem>>>(
        (const unsigned short*)zb, (const unsigned short*)w1b, fc1b,
        hpre_ptr, hpb, Bn, Hn, Dn,
        z, proto, ebias, topk, ban, tau, eps, cap, out);

    // 2) out_pre = h_pre @ fc2_w^T + fc2_b + router side block
    gemm_fused_kernel<0, 2, 16><<<dim3(17, 16), 256, gemm_smem>>>(
        (const unsigned short*)hpb, (const unsigned short*)w2b, fc2b,
        outpre_ptr, nullptr, Bn, Dn, Hn,
        z, proto, ebias, topk, ban, tau, eps, cap, out);

    // 3) adapter select + LoRA deltas + final combine
    adapter_kernel<<<Bn, 256>>>(z, ak, a1b, b1b, a2b, b2b, topk, out);
}

// round 14
// speedup vs baseline: 1.1844x; 1.0312x over previous
#include <cuda_runtime.h>
#include <math.h>

// Problem constants (fixed by the dataset)
#define Bn 2048
#define Dn 1024
#define Hn 2048
#define En 16
#define Wn 4
#define Rn 8
#define MAXK 4
#define CANDMAX 16
#define SCALE_C 1.0f

// ---------------- scratch (device globals; no allocation allowed) -----------
__device__ float g_hpre[Bn * Hn];
__device__ float g_outpre[Bn * Dn];
__device__ float g_cand_val[Bn * CANDMAX];
__device__ unsigned long long g_pack[Bn];
__device__ int   g_assigned_idx[Bn * MAXK];
__device__ float g_assigned_w[Bn * MAXK];
// bf16 (pair-packed) copies
__device__ unsigned g_z_bf[Bn * Dn / 2];
__device__ unsigned g_w1_bf[Hn * Dn / 2];
__device__ unsigned g_w2_bf[Dn * Hn / 2];
__device__ unsigned g_hpre_bf[Bn * Hn / 2];
__device__ unsigned g_a1_bf[En * Wn * Rn * Dn / 2];
__device__ unsigned g_b1_bf[En * Wn * Hn * Rn / 2];
__device__ unsigned g_a2_bf[En * Wn * Rn * Hn / 2];
__device__ unsigned g_b2_bf[En * Wn * Dn * Rn / 2];

// ---------------- output layout ----------------
struct Outs {
    float *z, *probs, *mask, *aidx, *aw, *chr, *ev_e, *ev_a;
};
__host__ __device__ __forceinline__ Outs make_outs(float* o, int k) {
    Outs s;
    s.z     = o; o += Bn * Dn;
    s.probs = o; o += Bn * En;
    s.mask  = o; o += Bn * En;
    s.aidx  = o; o += Bn * k;
    s.aw    = o; o += Bn * k;
    s.chr   = o; o += 1;
    s.ev_e  = o; o += (size_t)k * Bn;
    s.ev_a  = o;
    return s;
}

__device__ __forceinline__ float warp_reduce(float v) {
    #pragma unroll
    for (int off = 16; off; off >>= 1) v += __shfl_xor_sync(0xffffffffu, v, off);
    return v;
}
// fast silu (continuous outputs only; softmax keeps exact expf)
__device__ __forceinline__ float silu_f(float x) { return x / (1.0f + __expf(-x)); }

__device__ __forceinline__ unsigned pack_bf16(float lo, float hi) {
    unsigned r;
    asm("cvt.rn.bf16x2.f32 %0, %1, %2;" : "=r"(r) : "f"(hi), "f"(lo));
    return r;
}
__device__ __forceinline__ float bf_lo(unsigned u) { return __uint_as_float(u << 16); }
__device__ __forceinline__ float bf_hi(unsigned u) { return __uint_as_float(u & 0xffff0000u); }

__device__ __forceinline__ void mma_bf16(float* d, const unsigned* a, const unsigned* b) {
    asm volatile(
        "mma.sync.aligned.m16n8k16.row.col.f32.bf16.bf16.f32 "
        "{%0,%1,%2,%3}, {%4,%5,%6,%7}, {%8,%9}, {%0,%1,%2,%3};"
        : "+f"(d[0]), "+f"(d[1]), "+f"(d[2]), "+f"(d[3])
        : "r"(a[0]), "r"(a[1]), "r"(a[2]), "r"(a[3]), "r"(b[0]), "r"(b[1]));
}

__device__ __forceinline__ void cp_async16(unsigned* smem_dst, const void* gmem_src) {
    unsigned saddr = (unsigned)__cvta_generic_to_shared(smem_dst);
    asm volatile("cp.async.cg.shared.global [%0], [%1], 16;" :: "r"(saddr), "l"(gmem_src));
}
#define CP_COMMIT() asm volatile("cp.async.commit_group;")
#define CP_WAIT1()  asm volatile("cp.async.wait_group 1;")
#define GROUP_BAR(id) asm volatile("bar.sync %0, 128;" :: "r"(id) : "memory")

// =====================================================================
// Convert kernel: fp32 -> bf16x2-packed copies (one-time, elementwise).
// =====================================================================
#define CV0 (Bn * Dn / 2)
#define CV1 (CV0 + Hn * Dn / 2)
#define CV2 (CV1 + Dn * Hn / 2)
#define CV3 (CV2 + En * Wn * Rn * Dn / 2)
#define CV4 (CV3 + En * Wn * Hn * Rn / 2)
#define CV5 (CV4 + En * Wn * Rn * Hn / 2)
#define CV6 (CV5 + En * Wn * Dn * Rn / 2)

__global__ void __launch_bounds__(256)
convert_kernel(const float* __restrict__ z,  const float* __restrict__ w1,
               const float* __restrict__ w2, const float* __restrict__ a1,
               const float* __restrict__ b1, const float* __restrict__ a2,
               const float* __restrict__ b2) {
    for (int idx = blockIdx.x * 256 + threadIdx.x; idx < CV6; idx += gridDim.x * 256) {
        const float2* s; unsigned* d; int off;
        if      (idx < CV0) { s = (const float2*)z;  d = g_z_bf;  off = idx; }
        else if (idx < CV1) { s = (const float2*)w1; d = g_w1_bf; off = idx - CV0; }
        else if (idx < CV2) { s = (const float2*)w2; d = g_w2_bf; off = idx - CV1; }
        else if (idx < CV3) { s = (const float2*)a1; d = g_a1_bf; off = idx - CV2; }
        else if (idx < CV4) { s = (const float2*)b1; d = g_b1_bf; off = idx - CV3; }
        else if (idx < CV5) { s = (const float2*)a2; d = g_a2_bf; off = idx - CV4; }
        else                { s = (const float2*)b2; d = g_b2_bf; off = idx - CV5; }
        float2 v = s[off];
        d[off] = pack_bf16(v.x, v.y);
    }
}

// =====================================================================
// Side work A: logits/softmax/top-cand (fp32), one warp per token.
// =====================================================================
__device__ void logits_body(int b, int lane,
                            const float* __restrict__ z,
                            const float* __restrict__ proto,
                            const float* __restrict__ ebias,
                            const int* __restrict__ topk_p,
                            const int* __restrict__ ban_p,
                            const float* __restrict__ tau_p,
                            const float* __restrict__ eps_p,
                            float* __restrict__ d_out) {
    const float* zr = z + (size_t)b * Dn;

    float acc[En];
    #pragma unroll
    for (int e = 0; e < En; e++) acc[e] = 0.0f;
    for (int d = lane; d < Dn; d += 32) {
        float zv = zr[d];
        #pragma unroll
        for (int e = 0; e < En; e++) acc[e] += zv * proto[e * Dn + d];
    }
    #pragma unroll
    for (int e = 0; e < En; e++) acc[e] = warp_reduce(acc[e]);

    if (lane != 0) return;

    int k = *topk_p; if (k > En) k = En; if (k > MAXK) k = MAXK; if (k < 1) k = 1;
    int cand_k = 4 * k; if (cand_k < k) cand_k = k; if (cand_k > En) cand_k = En;
    int ban = *ban_p;
    float inv_tau = 1.0f / fmaxf(*tau_p, 1e-6f);
    float eps = *eps_p;

    float lg[En];
    float mx = -1e30f;
    #pragma unroll
    for (int e = 0; e < En; e++) {
        float v = acc[e] * inv_tau + ebias[e];
        if (e == ban) v = -1e9f;
        lg[e] = v;
        mx = fmaxf(mx, v);
    }
    float sum = 0.0f;
    #pragma unroll
    for (int e = 0; e < En; e++) { lg[e] = expf(lg[e] - mx); sum += lg[e]; }
    float inv = 1.0f / sum;

    Outs O = make_outs(d_out, k);
    float pr[En];
    #pragma unroll
    for (int e = 0; e < En; e++) {
        pr[e] = (1.0f - eps) * (lg[e] * inv) + eps / (float)En;
        O.probs[b * En + e] = pr[e];
        O.mask[b * En + e]  = 0.0f;
    }

    bool used[En];
    #pragma unroll
    for (int e = 0; e < En; e++) used[e] = false;
    unsigned long long pk = 0ull;
    for (int j = 0; j < cand_k; j++) {
        float bv = -1e30f; int bi = 0;
        for (int e = 0; e < En; e++)
            if (!used[e] && pr[e] > bv) { bv = pr[e]; bi = e; }
        used[bi] = true;
        g_cand_val[b * CANDMAX + j] = bv;
        pk |= ((unsigned long long)bi) << (4 * j);
    }
    g_pack[b] = pk;

    for (int s = 0; s < k; s++) {
        g_assigned_idx[b * MAXK + s] = -1;
        g_assigned_w[b * MAXK + s]   = 0.0f;
        O.aidx[b * k + s] = -1.0f;
        O.aw[b * k + s]   = 0.0f;
        O.ev_e[s * Bn + b] = -1.0f;
        O.ev_a[s * Bn + b] = -1.0f;
    }
}

// =====================================================================
// Side work B: batched greedy capacity router (single warp).
// =====================================================================
__device__ void route_body(int lane,
                           const int* __restrict__ topk_p,
                           const int* __restrict__ cap_p,
                           float* __restrict__ d_out) {
    int k = *topk_p; if (k > En) k = En; if (k > MAXK) k = MAXK; if (k < 1) k = 1;
    int cand_k = 4 * k; if (cand_k < k) cand_k = k; if (cand_k > En) cand_k = En;
    int cap_lim = *cap_p; if (cap_lim < 1) cap_lim = 1;

    Outs O = make_outs(d_out, k);

    int cap = 0;
    unsigned closed = 0;
    int hits = 0;

    int t0 = 0;
    while (t0 < Bn) {
        const int t = t0 + lane;
        const bool has = (t < Bn);
        unsigned long long pk = has ? g_pack[t] : 0ull;

        unsigned take = 0, slotcand = 0;
        int nslots = 0, myhits = 0;
        if (has) {
            for (int j = 0; j < cand_k; j++) {
                int e = (int)((pk >> (4 * j)) & 15ull);
                if (!((closed >> e) & 1u) && nslots < k) {
                    take |= (1u << e);
                    slotcand |= ((unsigned)j) << (4 * nslots);
                    if (j > 0) myhits++;
                    nslots++;
                }
            }
        }

        unsigned mybits = 0;
        #pragma unroll
        for (int e = 0; e < En; e++) {
            unsigned bb = __ballot_sync(0xffffffffu, (take >> e) & 1u);
            if (lane == e) mybits = bb;
        }
        int cnt = __popc(mybits);

        bool viol = (lane < En) && !((closed >> lane) & 1u) && (cap + cnt > cap_lim);
        unsigned vm = __ballot_sync(0xffffffffu, viol);
        int pstar = 32;
        if (vm) {
            int myp = 32;
            if (viol) {
                int rem = cap_lim - cap;
                unsigned m = mybits;
                for (int i = 0; i < rem; i++) m &= m - 1;
                myp = __ffs(m) - 1;
            }
            #pragma unroll
            for (int off = 16; off; off >>= 1) {
                int o = __shfl_xor_sync(0xffffffffu, myp, off);
                myp = min(myp, o);
            }
            pstar = myp;
        }

        unsigned commit_prefix = (pstar >= 32) ? 0xffffffffu : ((1u << pstar) - 1u);
        if (lane < En) cap += __popc(mybits & commit_prefix);

        if (has && lane < pstar) {
            for (int s = 0; s < nslots; s++) {
                int j = (int)((slotcand >> (4 * s)) & 15u);
                int e = (int)((pk >> (4 * j)) & 15ull);
                float v = g_cand_val[t * CANDMAX + j];
                g_assigned_idx[t * MAXK + s] = e;
                g_assigned_w[t * MAXK + s]   = v;
                O.aidx[t * k + s] = (float)e;
                O.aw[t * k + s]   = v;
                O.ev_e[s * Bn + t] = (float)e;
                O.mask[t * En + e] = 1.0f;
            }
            hits += myhits;
        }

        closed = __ballot_sync(0xffffffffu, (lane < En) && (cap >= cap_lim)) & 0xffffu;
        t0 += pstar;
    }

    #pragma unroll
    for (int off = 16; off; off >>= 1) hits += __shfl_xor_sync(0xffffffffu, hits, off);
    if (lane == 0) O.chr[0] = (float)hits / (float)(Bn * k);
}

// =====================================================================
// Fused BF16 GEMM + side work.
// Block tile 128x128x32, 8 warps, warp tile 32x64, m16n8k16.
// 3-stage cp.async pipeline: stage = 256 rows x 20 uints = 20,480 B;
// 3 stages = 61,440 B -> 2 blocks/SM. Same conflict-free PITCH=20 map.
// Accumulation order over K identical to previous tiles (bit-identical C).
// SIDE==1: logits side blocks; SIDE==2: router side block.
// =====================================================================
#define TBM 128
#define TBN 128
#define TBK 32
#define PITCH 20
#define STG ((TBM + TBN) * PITCH)
#define NSTAGE 3

template <int ACT, int SIDE, int NX>
__global__ void __launch_bounds__(256, 2)
gemm_fused_kernel(const unsigned short* __restrict__ Abf,
                  const unsigned short* __restrict__ Wbf,
                  const float* __restrict__ bias, float* __restrict__ C,
                  unsigned* __restrict__ Cbf,
                  int M, int N, int K,
                  const float* __restrict__ z, const float* __restrict__ proto,
                  const float* __restrict__ ebias,
                  const int* __restrict__ topk_p, const int* __restrict__ ban_p,
                  const float* __restrict__ tau_p, const float* __restrict__ eps_p,
                  const int* __restrict__ cap_p,
                  float* __restrict__ d_out) {
    const int bx = blockIdx.x;
    const int by = blockIdx.y;
    const int tid = threadIdx.x;
    const int warp = tid >> 5;
    const int lane = tid & 31;

    if (bx >= NX) {
        if (SIDE == 1) {
            int blk = (bx - NX) * gridDim.y + by;
            int b = blk * 8 + warp;
            if (b < Bn)
                logits_body(b, lane, z, proto, ebias, topk_p, ban_p, tau_p, eps_p, d_out);
        } else if (SIDE == 2) {
            if (by == 0 && warp == 0)
                route_body(lane, topk_p, cap_p, d_out);
        }
        return;
    }

    extern __shared__ unsigned smem_u[];

    const int g  = lane >> 2;
    const int tg = lane & 3;
    const int wq  = warp & 3;   // warp m index (0..3), 32 rows each
    const int wn2 = warp >> 2;  // warp n index (0..1), 64 cols each

    float acc[2][8][4];
    #pragma unroll
    for (int i = 0; i < 2; i++)
        #pragma unroll
        for (int j = 0; j < 8; j++)
            #pragma unroll
            for (int c = 0; c < 4; c++) acc[i][j][c] = 0.0f;

    // staging: 256 rows x 4 chunks(16B) = 1024 chunks -> 4 per thread
    auto issue = [&](int buf, int kt) {
        unsigned* base = smem_u + buf * STG;
        const int k0 = kt * TBK;
        #pragma unroll
        for (int i = 0; i < 4; i++) {
            int c = tid + i * 256;
            int row = c >> 2, ch = c & 3;
            const unsigned short* src;
            if (row < TBM) src = Abf + (size_t)(by * TBM + row) * K + k0 + ch * 8;
            else           src = Wbf + (size_t)(bx * TBN + row - TBM) * K + k0 + ch * 8;
            cp_async16(base + row * PITCH + ch * 4, (const void*)src);
        }
    };

    const int KIT = K / TBK;
    issue(0, 0); CP_COMMIT();
    if (1 < KIT) { issue(1, 1); } CP_COMMIT();

    int buf = 0;
    for (int kt = 0; kt < KIT; kt++) {
        CP_WAIT1();
        __syncthreads();
        // issue next into the buffer freed by the barrier (kt-1's buffer)
        if (kt + 2 < KIT) {
            int nb = buf + 2; if (nb >= NSTAGE) nb -= NSTAGE;
            issue(nb, kt + 2);
        }
        CP_COMMIT();

        const unsigned* AsC = smem_u + buf * STG;
        const unsigned* BsC = AsC + TBM * PITCH;

        #pragma unroll
        for (int kk = 0; kk < 2; kk++) {
            unsigned afr[2][4];
            #pragma unroll
            for (int mi = 0; mi < 2; mi++) {
                int row = wq * 32 + mi * 16 + g;
                afr[mi][0] = AsC[row * PITCH + kk * 8 + tg];
                afr[mi][1] = AsC[(row + 8) * PITCH + kk * 8 + tg];
                afr[mi][2] = AsC[row * PITCH + kk * 8 + tg + 4];
                afr[mi][3] = AsC[(row + 8) * PITCH + kk * 8 + tg + 4];
            }
            unsigned bfr[8][2];
            #pragma unroll
            for (int ni = 0; ni < 8; ni++) {
                int col = wn2 * 64 + ni * 8 + g;
                bfr[ni][0] = BsC[col * PITCH + kk * 8 + tg];
                bfr[ni][1] = BsC[col * PITCH + kk * 8 + tg + 4];
            }
            #pragma unroll
            for (int mi = 0; mi < 2; mi++)
                #pragma unroll
                for (int ni = 0; ni < 8; ni++)
                    mma_bf16(acc[mi][ni], afr[mi], bfr[ni]);
        }
        buf++; if (buf >= NSTAGE) buf = 0;
    }

    #pragma unroll
    for (int mi = 0; mi < 2; mi++) {
        int row0 = by * TBM + wq * 32 + mi * 16 + g;
        #pragma unroll
        for (int ni = 0; ni < 8; ni++) {
            int col = bx * TBN + wn2 * 64 + ni * 8 + 2 * tg;
            float b0 = bias[col], b1 = bias[col + 1];
            float v0 = acc[mi][ni][0] + b0;
            float v1 = acc[mi][ni][1] + b1;
            float v2 = acc[mi][ni][2] + b0;
            float v3 = acc[mi][ni][3] + b1;
            if (ACT) { v0 = silu_f(v0); v1 = silu_f(v1); v2 = silu_f(v2); v3 = silu_f(v3); }
            *(float2*)(&C[(size_t)row0 * N + col])       = make_float2(v0, v1);
            *(float2*)(&C[(size_t)(row0 + 8) * N + col]) = make_float2(v2, v3);
            if (ACT) {
                Cbf[((size_t)row0 * N + col) >> 1]       = pack_bf16(v0, v1);
                Cbf[((size_t)(row0 + 8) * N + col) >> 1] = pack_bf16(v2, v3);
            }
        }
    }
}

// =====================================================================
// Adapter kernel (exact round-13 version: 50.0 us measured).
// =====================================================================
__global__ void __launch_bounds__(256)
adapter_kernel(const float* __restrict__ z,
               const float* __restrict__ ak,
               const unsigned* __restrict__ a1b, const unsigned* __restrict__ b1b,
               const unsigned* __restrict__ a2b, const unsigned* __restrict__ b2b,
               const int* __restrict__ topk_p,
               float* __restrict__ d_out) {
    __shared__ float s_z[Dn];
    __shared__ float s_hp[Hn];
    __shared__ float s_t1[2][Rn];
    __shared__ float s_t2p[2][4][Rn];
    __shared__ float s_sc[2][Wn];
    __shared__ int   s_base[2];
    __shared__ float s_wgt[2];
    __shared__ int   s_valid[2];

    const int b = blockIdx.x;
    const int tid = threadIdx.x;
    const int lane = tid & 31;
    const int warp = tid >> 5;
    const int group = warp >> 2;
    const int wig = warp & 3;
    const int gt = tid & 127;
    const int gbar = 1 + group;

    int k = *topk_p; if (k > En) k = En; if (k > MAXK) k = MAXK; if (k < 1) k = 1;
    Outs O = make_outs(d_out, k);

    for (int i = tid; i < Dn / 4; i += 256)
        ((float4*)s_z)[i] = ((const float4*)(z + (size_t)b * Dn))[i];
    for (int i = tid; i < Hn / 4; i += 256)
        ((float4*)s_hp)[i] = ((const float4*)(g_hpre + (size_t)b * Hn))[i];

    float opre[Dn / 256];
    float accd[Dn / 256];
    #pragma unroll
    for (int i = 0; i < Dn / 256; i++) {
        opre[i] = g_outpre[(size_t)b * Dn + tid + i * 256];
        accd[i] = 0.0f;
    }
    __syncthreads();

    for (int s0 = 0; s0 < k; s0 += 2) {
        const int sA = s0 + group;
        const bool act = (sA < k);
        int e = -1;
        float wgt = 0.0f;
        if (act) {
            e   = g_assigned_idx[b * MAXK + sA];
            wgt = g_assigned_w[b * MAXK + sA];
        }
        const bool valid = act && (e >= 0);

        if (valid) {
            const float4* akr = (const float4*)(ak + (size_t)(e * Wn + wig) * Dn);
            float p = 0.0f;
            #pragma unroll
            for (int i = 0; i < Dn / 128; i++) {
                int idx = lane + i * 32;
                float4 a = akr[idx];
                float4 zz = ((const float4*)s_z)[idx];
                p += a.x * zz.x + a.y * zz.y + a.z * zz.z + a.w * zz.w;
            }
            p = warp_reduce(p);
            if (lane == 0) s_sc[group][wig] = p;
        }
        GROUP_BAR(gbar);

        if (gt == 0) {
            if (valid) {
                float bv = s_sc[group][0]; int bi = 0;
                #pragma unroll
                for (int w2 = 1; w2 < Wn; w2++)
                    if (s_sc[group][w2] > bv) { bv = s_sc[group][w2]; bi = w2; }
                s_base[group] = e * Wn + bi;
                s_wgt[group] = wgt;
                s_valid[group] = 1;
                O.ev_a[sA * Bn + b] = (float)bi;
            } else {
                s_valid[group] = 0;
            }
        }
        GROUP_BAR(gbar);

        const int base = s_base[group];

        if (valid) {
            const uint2* A1r0 = (const uint2*)a1b + ((size_t)base * Rn + 2 * wig) * (Dn / 4);
            const uint2* A1r1 = A1r0 + (Dn / 4);
            float q0 = 0.0f, q1 = 0.0f;
            #pragma unroll
            for (int i = 0; i < Dn / 128; i++) {
                int idx = lane + i * 32;
                float4 zz = ((const float4*)s_z)[idx];
                uint2 u0 = A1r0[idx], u1 = A1r1[idx];
                q0 += zz.x * bf_lo(u0.x) + zz.y * bf_hi(u0.x)
                    + zz.z * bf_lo(u0.y) + zz.w * bf_hi(u0.y);
                q1 += zz.x * bf_lo(u1.x) + zz.y * bf_hi(u1.x)
                    + zz.z * bf_lo(u1.y) + zz.w * bf_hi(u1.y);
            }
            q0 = warp_reduce(q0);
            q1 = warp_reduce(q1);
            if (lane == 0) { s_t1[group][2 * wig] = q0; s_t1[group][2 * wig + 1] = q1; }
        }
        GROUP_BAR(gbar);

        if (valid) {
            float t1r[Rn];
            #pragma unroll
            for (int r = 0; r < Rn; r++) t1r[r] = s_t1[group][r];
            float t2p[Rn];
            #pragma unroll
            for (int r = 0; r < Rn; r++) t2p[r] = 0.0f;
            const uint4* B1 = (const uint4*)b1b + (size_t)base * Hn;
            const unsigned* A2 = a2b + (size_t)base * Rn * (Hn / 2);
            #pragma unroll
            for (int i = 0; i < 8; i++) {
                int hp = wig * 256 + lane + i * 32;
                float2 h2 = *(const float2*)&s_hp[2 * hp];
                uint4 q0 = B1[2 * hp];
                uint4 q1 = B1[2 * hp + 1];
                float d10 = t1r[0] * bf_lo(q0.x) + t1r[1] * bf_hi(q0.x)
                          + t1r[2] * bf_lo(q0.y) + t1r[3] * bf_hi(q0.y)
                          + t1r[4] * bf_lo(q0.z) + t1r[5] * bf_hi(q0.z)
                          + t1r[6] * bf_lo(q0.w) + t1r[7] * bf_hi(q0.w);
                float d11 = t1r[0] * bf_lo(q1.x) + t1r[1] * bf_hi(q1.x)
                          + t1r[2] * bf_lo(q1.y) + t1r[3] * bf_hi(q1.y)
                          + t1r[4] * bf_lo(q1.z) + t1r[5] * bf_hi(q1.z)
                          + t1r[6] * bf_lo(q1.w) + t1r[7] * bf_hi(q1.w);
                float hv0 = silu_f(h2.x + d10 * SCALE_C);
                float hv1 = silu_f(h2.y + d11 * SCALE_C);
                #pragma unroll
                for (int r = 0; r < Rn; r++) {
                    unsigned u = A2[r * (Hn / 2) + hp];
                    t2p[r] += hv0 * bf_lo(u) + hv1 * bf_hi(u);
                }
            }
            #pragma unroll
            for (int r = 0; r < Rn; r++) t2p[r] = warp_reduce(t2p[r]);
            if (lane < Rn) s_t2p[group][wig][lane] = t2p[lane];
        }
        __syncthreads();

        #pragma unroll
        for (int gg = 0; gg < 2; gg++) {
            if (s_valid[gg]) {
                const int bs = s_base[gg];
                const float wg = s_wgt[gg];
                float t2r[Rn];
                #pragma unroll
                for (int r = 0; r < Rn; r++)
                    t2r[r] = s_t2p[gg][0][r] + s_t2p[gg][1][r]
                           + s_t2p[gg][2][r] + s_t2p[gg][3][r];
                const uint4* B2q = (const uint4*)b2b + (size_t)bs * Dn;
                #pragma unroll
                for (int i = 0; i < Dn / 256; i++) {
                    int d = tid + i * 256;
                    uint4 q = B2q[d];
                    float d2 = t2r[0] * bf_lo(q.x) + t2r[1] * bf_hi(q.x)
                             + t2r[2] * bf_lo(q.y) + t2r[3] * bf_hi(q.y)
                             + t2r[4] * bf_lo(q.z) + t2r[5] * bf_hi(q.z)
                             + t2r[6] * bf_lo(q.w) + t2r[7] * bf_hi(q.w);
                    accd[i] += wg * (opre[i] + d2 * SCALE_C);
                }
            }
        }
        __syncthreads();
    }

    #pragma unroll
    for (int i = 0; i < Dn / 256; i++) {
        int d = tid + i * 256;
        O.z[(size_t)b * Dn + d] = s_z[d] + accd[i];
    }
}

// =====================================================================
// launch
// =====================================================================
extern "C" void kernel_launch(void* const* d_in, const int* in_sizes, int n_in,
                              void* d_out, int out_size) {
    const float* z     = (const float*)d_in[0];
    const int*   topk  = (const int*)  d_in[1];
    const int*   cap   = (const int*)  d_in[2];
    const int*   ban   = (const int*)  d_in[3];
    const float* tau   = (const float*)d_in[4];
    const float* eps   = (const float*)d_in[5];
    const float* fc1w  = (const float*)d_in[6];
    const float* fc1b  = (const float*)d_in[7];
    const float* fc2w  = (const float*)d_in[8];
    const float* fc2b  = (const float*)d_in[9];
    const float* proto = (const float*)d_in[10];
    const float* ak    = (const float*)d_in[11];
    const float* ebias = (const float*)d_in[12];
    const float* a1    = (const float*)d_in[13];
    const float* b1    = (const float*)d_in[14];
    const float* a2    = (const float*)d_in[15];
    const float* b2    = (const float*)d_in[16];
    float* out = (float*)d_out;

    float *hpre_ptr, *outpre_ptr;
    unsigned *zb, *w1b, *w2b, *hpb, *a1b, *b1b, *a2b, *b2b;
    cudaGetSymbolAddress((void**)&hpre_ptr, g_hpre);
    cudaGetSymbolAddress((void**)&outpre_ptr, g_outpre);
    cudaGetSymbolAddress((void**)&zb,  g_z_bf);
    cudaGetSymbolAddress((void**)&w1b, g_w1_bf);
    cudaGetSymbolAddress((void**)&w2b, g_w2_bf);
    cudaGetSymbolAddress((void**)&hpb, g_hpre_bf);
    cudaGetSymbolAddress((void**)&a1b, g_a1_bf);
    cudaGetSymbolAddress((void**)&b1b, g_b1_bf);
    cudaGetSymbolAddress((void**)&a2b, g_a2_bf);
    cudaGetSymbolAddress((void**)&b2b, g_b2_bf);

    const int gemm_smem = NSTAGE * STG * sizeof(unsigned);  // 61440
    cudaFuncSetAttribute((const void*)gemm_fused_kernel<1, 1, 16>,
                         cudaFuncAttributeMaxDynamicSharedMemorySize, gemm_smem);
    cudaFuncSetAttribute((const void*)gemm_fused_kernel<0, 2, 8>,
                         cudaFuncAttributeMaxDynamicSharedMemorySize, gemm_smem);

    // 0) one-time fp32 -> bf16 conversion
    convert_kernel<<<2048, 256>>>(z, fc1w, fc2w, a1, b1, a2, b2);

    // 1) h_pre = silu(z @ fc1_w^T + fc1_b) (+ bf16 copy) + logits side work
    //    grid: 16 gemm n-cols (2048/128) x 16 m-rows + 16 logits cols
    gemm_fused_kernel<1, 1, 16><<<dim3(32, 16), 256, gemm_smem>>>(
        (const unsigned short*)zb, (const unsigned short*)w1b, fc1b,
        hpre_ptr, hpb, Bn, Hn, Dn,
        z, proto, ebias, topk, ban, tau, eps, cap, out);

    // 2) out_pre = h_pre @ fc2_w^T + fc2_b + router side block
    //    grid: 8 gemm n-cols (1024/128) x 16 m-rows + 1 router col
    gemm_fused_kernel<0, 2, 8><<<dim3(9, 16), 256, gemm_smem>>>(
        (const unsigned short*)hpb, (const unsigned short*)w2b, fc2b,
        outpre_ptr, nullptr, Bn, Dn, Hn,
        z, proto, ebias, topk, ban, tau, eps, cap, out);

    // 3) adapter select + LoRA deltas + final combine (round-13 exact)
    adapter_kernel<<<Bn, 256>>>(z, ak, a1b, b1b, a2b, b2b, topk, out);
}